// round 3
// baseline (speedup 1.0000x reference)
#include <cuda_runtime.h>
#include <math.h>

#define NN 4096
#define NEG_INF -1e9f

// ---------------- scratch (device globals; no allocation allowed) ----------------
__device__ __align__(16) float g_mask[(size_t)NN * NN];   // 64MB mask scratch
__device__ __align__(16) float g_NW[(size_t)NN * 512];    // [n][512]: cols 0-255 proj (h*64+o), 256-511 skip
__device__ __align__(16) float g_ab[NN * 8];              // [n][8]: 0-3 s_src(a), 4-7 s_tgt(b)
__device__ __align__(16) float g_W512[128 * 512];         // combined weights [f_in][512]
__device__ __align__(16) float g_Wab[128 * 8];            // combined score weights [f_in][8]
__device__ __align__(16) float g_den[NN * 4];             // [j][h] softmax denominators
__device__ __align__(16) float g_inv[NN * 4];             // [j][h] 1/denom

// packed fp32x2 helpers (Blackwell)
#define FMA2(acc, p, w) asm("fma.rn.f32x2 %0, %1, %2, %3;" : "=l"(acc) : "l"(p), "l"(w), "l"(acc))
#define DUP2(d, f)      asm("mov.b64 %0, {%1, %1};" : "=l"(d) : "f"(f))

// ---------------- K_prep: build combined weights, zero denominators ----------------
__global__ void k_prep(const float* __restrict__ pp, const float* __restrict__ ssrc,
                       const float* __restrict__ stgt, const float* __restrict__ skw) {
    int idx = blockIdx.x * 256 + threadIdx.x;   // grid 256 -> 65536 threads
    if (idx < 128 * 512) {
        int f = idx >> 9, c = idx & 511;
        float v;
        if (c < 256) { int h = c >> 6, o = c & 63; v = pp[h * 128 * 64 + f * 64 + o]; }
        else         { int cc = c - 256;           v = skw[cc * 128 + f]; }
        g_W512[f * 512 + c] = v;
    }
    if (idx < 128 * 8) {
        int f = idx >> 3, c = idx & 7;
        int h = c & 3;
        const float* sc = (c < 4) ? ssrc : stgt;
        float acc = 0.f;
        #pragma unroll
        for (int o = 0; o < 64; ++o) acc += pp[h * 128 * 64 + f * 64 + o] * sc[h * 64 + o];
        g_Wab[f * 8 + c] = acc;
    }
    if (idx < NN * 4) g_den[idx] = 0.f;   // must re-zero every launch (graph replay)
}

// ---------------- K0b: NW = nodes[4096x128] @ W512[128x512] ----------------
__global__ void __launch_bounds__(256) k_gemm_nw(const float* __restrict__ nodes) {
    __shared__ float sN[32][128];
    __shared__ float sW[32][128];
    int t = threadIdx.x;
    int r0 = blockIdx.x * 32;
    int c0 = blockIdx.y * 128;
    #pragma unroll
    for (int k = 0; k < 16; ++k) {
        int e = t + k * 256; int kk = e & 127, rr = e >> 7;
        sN[rr][kk] = nodes[(r0 + rr) * 128 + kk];
    }
    float acc[4][4] = {};
    int rg = t >> 5, cg = t & 31;
    for (int kc = 0; kc < 4; ++kc) {
        __syncthreads();
        #pragma unroll
        for (int k = 0; k < 16; ++k) {   // FIX: 32x128 tile needs 16 iters of 256 threads
            int e = t + k * 256; int cc = e & 127, kk = e >> 7;
            sW[kk][cc] = g_W512[(kc * 32 + kk) * 512 + c0 + cc];
        }
        __syncthreads();
        #pragma unroll
        for (int k = 0; k < 32; ++k) {
            float4 b = *(const float4*)&sW[k][cg * 4];
            #pragma unroll
            for (int q = 0; q < 4; ++q) {
                float a = sN[rg * 4 + q][kc * 32 + k];
                acc[q][0] += a * b.x; acc[q][1] += a * b.y;
                acc[q][2] += a * b.z; acc[q][3] += a * b.w;
            }
        }
    }
    #pragma unroll
    for (int q = 0; q < 4; ++q) {
        float4 v = make_float4(acc[q][0], acc[q][1], acc[q][2], acc[q][3]);
        *(float4*)&g_NW[(size_t)(r0 + rg * 4 + q) * 512 + c0 + cg * 4] = v;
    }
}

// ---------------- K0c: ab = nodes @ Wab (s_src, s_tgt per head) ----------------
__global__ void k_ab(const float* __restrict__ nodes) {
    int idx = blockIdx.x * 256 + threadIdx.x;   // grid 128 -> 32768
    int n = idx >> 3, c = idx & 7;
    float acc = 0.f;
    #pragma unroll 8
    for (int f = 0; f < 128; ++f) acc += __ldg(&nodes[n * 128 + f]) * g_Wab[f * 8 + c];
    g_ab[idx] = acc;
}

// ---------------- K_A: mask + column softmax denominators (no-max softmax) ----------------
__global__ void __launch_bounds__(256) k_passA(const float* __restrict__ deg,
                                               const float* __restrict__ bond,
                                               const float* __restrict__ cutp) {
    __shared__ float4 sa[64];
    int t = threadIdx.x;
    int j = blockIdx.x * 256 + t;
    int i0 = blockIdx.y * 256;
    float cut = cutp[0];   // value is 0; int32-bits-0 == 0.0f either way
    float4 b4 = *(const float4*)&g_ab[j * 8 + 4];
    float d0 = 0.f, d1 = 0.f, d2 = 0.f, d3 = 0.f;
    for (int ic = 0; ic < 4; ++ic) {
        __syncthreads();
        if (t < 64) sa[t] = *(const float4*)&g_ab[(i0 + ic * 64 + t) * 8];
        __syncthreads();
        int ibase = i0 + ic * 64;
        #pragma unroll 4
        for (int il = 0; il < 64; ++il) {
            size_t off = (size_t)(ibase + il) * NN + j;
            float dd = deg[off], bb = bond[off];
            float wdm = dd + bb;
            float m = (wdm > 0.f) ? wdm : ((bb > cut) ? (bb + wdm) : NEG_INF);
            g_mask[off] = m;
            float4 a = sa[il];
            float x0 = a.x + b4.x; x0 = fmaxf(x0, 0.2f * x0); d0 += __expf(x0 + m);
            float x1 = a.y + b4.y; x1 = fmaxf(x1, 0.2f * x1); d1 += __expf(x1 + m);
            float x2 = a.z + b4.z; x2 = fmaxf(x2, 0.2f * x2); d2 += __expf(x2 + m);
            float x3 = a.w + b4.w; x3 = fmaxf(x3, 0.2f * x3); d3 += __expf(x3 + m);
        }
    }
    atomicAdd(&g_den[j * 4 + 0], d0);
    atomicAdd(&g_den[j * 4 + 1], d1);
    atomicAdd(&g_den[j * 4 + 2], d2);
    atomicAdd(&g_den[j * 4 + 3], d3);
}

__global__ void k_inv() {
    int i = blockIdx.x * 256 + threadIdx.x;   // grid 64 -> 16384
    g_inv[i] = 1.0f / g_den[i];
}

// ---------------- K_LN: layernorm of mask rows -> second output ----------------
__global__ void __launch_bounds__(256) k_ln(float* __restrict__ outln) {
    __shared__ float red[256];
    __shared__ float red2[256];
    int r = blockIdx.x, t = threadIdx.x;
    const float4* row = (const float4*)&g_mask[(size_t)r * NN];
    float4 v[4];
    float s = 0.f, sq = 0.f;
    #pragma unroll
    for (int k = 0; k < 4; ++k) {
        v[k] = row[t + k * 256];
        s  += v[k].x + v[k].y + v[k].z + v[k].w;
        sq += v[k].x * v[k].x + v[k].y * v[k].y + v[k].z * v[k].z + v[k].w * v[k].w;
    }
    red[t] = s; red2[t] = sq;
    __syncthreads();
    for (int off = 128; off > 0; off >>= 1) {
        if (t < off) { red[t] += red[t + off]; red2[t] += red2[t + off]; }
        __syncthreads();
    }
    float mu  = red[0] * (1.0f / NN);
    float var = red2[0] * (1.0f / NN) - mu * mu;
    float rstd = rsqrtf(var + 1e-5f);
    float4* o = (float4*)&outln[(size_t)r * NN];
    #pragma unroll
    for (int k = 0; k < 4; ++k) {
        float4 w = v[k];
        w.x = (w.x - mu) * rstd; w.y = (w.y - mu) * rstd;
        w.z = (w.z - mu) * rstd; w.w = (w.w - mu) * rstd;
        o[t + k * 256] = w;
    }
}

// ---------------- K_C: attention aggregation + skip + ELU (fp32x2) ----------------
// block: 16 output rows x 256 cols (4 heads x 64), loop over j in chunks of 32.
__global__ void __launch_bounds__(256) k_passC(float* __restrict__ out) {
    __shared__ float  sM[16][33];          // mask tile
    __shared__ float  sP[4][32][16];       // P[h][jj][il]
    __shared__ float  sW[4][32][64];       // w[h][jj][f] (inv_denom folded in)
    __shared__ float4 sa4[16];             // a for block rows
    __shared__ float4 sb4[32];             // b for chunk cols
    __shared__ float4 sinv4[32];           // inv_denom for chunk cols

    int t = threadIdx.x;
    int i0 = blockIdx.x * 16;
    if (t < 16) sa4[t] = *(const float4*)&g_ab[(i0 + t) * 8];

    int rg = t & 3, cg = t >> 2;
    int h = cg >> 4, c0 = (cg & 15) * 4;
    int r0 = rg * 4;

    unsigned long long a00 = 0ull, a01 = 0ull, a02 = 0ull, a03 = 0ull;
    unsigned long long a10 = 0ull, a11 = 0ull, a12 = 0ull, a13 = 0ull;

    for (int ch = 0; ch < 128; ++ch) {
        int j0 = ch * 32;
        __syncthreads();
        // phase 1: mask tile + per-column scalars
        {
            int e = t;       { int jj = e & 31, il = e >> 5; sM[il][jj] = g_mask[(size_t)(i0 + il) * NN + j0 + jj]; }
            e = t + 256;     { int jj = e & 31, il = e >> 5; sM[il][jj] = g_mask[(size_t)(i0 + il) * NN + j0 + jj]; }
            if (t < 32)           sb4[t]        = *(const float4*)&g_ab[(j0 + t) * 8 + 4];
            else if (t < 64)      sinv4[t - 32] = *(const float4*)&g_inv[(j0 + t - 32) * 4];
        }
        __syncthreads();
        // phase 2: compute P (exp) and stage w
        #pragma unroll
        for (int k = 0; k < 8; ++k) {
            int e = t + k * 256;
            int il = e & 15, jj = (e >> 4) & 31, hh = e >> 9;
            float a = ((const float*)&sa4[il])[hh];
            float b = ((const float*)&sb4[jj])[hh];
            float x = a + b; x = fmaxf(x, 0.2f * x);
            sP[hh][jj][il] = __expf(x + sM[il][jj]);
        }
        #pragma unroll
        for (int k = 0; k < 32; ++k) {
            int e = t + k * 256;
            int f = e & 63, jj = (e >> 6) & 31, hh = e >> 11;
            sW[hh][jj][f] = g_NW[(size_t)(j0 + jj) * 512 + hh * 64 + f] * ((const float*)&sinv4[jj])[hh];
        }
        __syncthreads();
        // phase 3: FMA (packed f32x2: pairs of rows per 64-bit acc)
        #pragma unroll 4
        for (int jj = 0; jj < 32; ++jj) {
            const float* Pp = &sP[h][jj][r0];
            unsigned long long pd0 = *(const unsigned long long*)(Pp);      // rows r0, r0+1
            unsigned long long pd1 = *(const unsigned long long*)(Pp + 2);  // rows r0+2, r0+3
            float4 w = *(const float4*)&sW[h][jj][c0];
            unsigned long long wd;
            DUP2(wd, w.x); FMA2(a00, pd0, wd); FMA2(a10, pd1, wd);
            DUP2(wd, w.y); FMA2(a01, pd0, wd); FMA2(a11, pd1, wd);
            DUP2(wd, w.z); FMA2(a02, pd0, wd); FMA2(a12, pd1, wd);
            DUP2(wd, w.w); FMA2(a03, pd0, wd); FMA2(a13, pd1, wd);
        }
    }

    // epilogue: + skip, ELU, store
    float2 u00 = *(float2*)&a00, u01 = *(float2*)&a01, u02 = *(float2*)&a02, u03 = *(float2*)&a03;
    float2 u10 = *(float2*)&a10, u11 = *(float2*)&a11, u12 = *(float2*)&a12, u13 = *(float2*)&a13;
    int gc = h * 64 + c0;
    float rowvals[4][4] = {
        { u00.x, u01.x, u02.x, u03.x },
        { u00.y, u01.y, u02.y, u03.y },
        { u10.x, u11.x, u12.x, u13.x },
        { u10.y, u11.y, u12.y, u13.y },
    };
    #pragma unroll
    for (int rr = 0; rr < 4; ++rr) {
        int row = i0 + r0 + rr;
        float4 sk = *(const float4*)&g_NW[(size_t)row * 512 + 256 + gc];
        float v0 = rowvals[rr][0] + sk.x;
        float v1 = rowvals[rr][1] + sk.y;
        float v2 = rowvals[rr][2] + sk.z;
        float v3 = rowvals[rr][3] + sk.w;
        v0 = (v0 > 0.f) ? v0 : expm1f(v0);
        v1 = (v1 > 0.f) ? v1 : expm1f(v1);
        v2 = (v2 > 0.f) ? v2 : expm1f(v2);
        v3 = (v3 > 0.f) ? v3 : expm1f(v3);
        *(float4*)&out[(size_t)row * 256 + gc] = make_float4(v0, v1, v2, v3);
    }
}

// ---------------- launch ----------------
extern "C" void kernel_launch(void* const* d_in, const int* in_sizes, int n_in,
                              void* d_out, int out_size) {
    const float* nodes = (const float*)d_in[0];
    const float* deg   = (const float*)d_in[1];
    // d_in[2] = edges_features_distance (unused by reference)
    const float* bond  = (const float*)d_in[3];
    const float* pp    = (const float*)d_in[4];
    const float* ssrc  = (const float*)d_in[5];
    const float* stgt  = (const float*)d_in[6];
    const float* skw   = (const float*)d_in[7];
    const float* cutp  = (const float*)d_in[8];   // value 0: int32/float32 bits identical

    float* out = (float*)d_out;                   // [0, 4096*256): out ; then mask_ln
    float* outln = out + (size_t)NN * 256;

    k_prep<<<256, 256>>>(pp, ssrc, stgt, skw);
    k_gemm_nw<<<dim3(128, 4), 256>>>(nodes);
    k_ab<<<128, 256>>>(nodes);
    k_passA<<<dim3(16, 16), 256>>>(deg, bond, cutp);
    k_inv<<<64, 256>>>();
    k_ln<<<NN, 256>>>(outln);
    k_passC<<<256, 256>>>(out);
}

// round 6
// speedup vs baseline: 1.5047x; 1.5047x over previous
#include <cuda_runtime.h>
#include <cuda_bf16.h>
#include <math.h>
#include <stdint.h>

#define NN 4096
#define NEG_INF -1e9f
#define L2E 1.4426950408889634f

// ---------------- scratch (device globals; no allocation allowed) ----------------
__device__ __align__(16) float g_mask[(size_t)NN * NN];       // 64MB mask scratch
__device__ __align__(16) float g_NW[(size_t)NN * 512];        // [n][512]: 0-255 proj, 256-511 skip
__device__ __align__(16) unsigned short g_Whi[(size_t)256 * NN]; // bf16 hi of W^T[hf][j]*inv
__device__ __align__(16) unsigned short g_Wlo[(size_t)256 * NN]; // bf16 lo residual
__device__ __align__(16) float g_ab[NN * 8];                  // [n][8]: 0-3 s_src(a), 4-7 s_tgt(b)
__device__ __align__(16) float g_W512[128 * 512];             // combined weights [f_in][512]
__device__ __align__(16) float g_Wab[128 * 8];                // combined score weights
__device__ __align__(16) float g_den[NN * 4];                 // [j][h] softmax denominators
__device__ __align__(16) float g_inv[NN * 4];                 // [j][h] 1/denom

__device__ __forceinline__ uint32_t smem_u32(const void* p) {
    uint32_t a;
    asm("{ .reg .u64 tmp; cvta.to.shared.u64 tmp, %1; cvt.u32.u64 %0, tmp; }" : "=r"(a) : "l"(p));
    return a;
}

// bf16 mma m16n8k16 (base-target HMMA; no tcgen05 — compute_103 compatible)
__device__ __forceinline__ void mma_bf16(float* d, const uint32_t* a, uint32_t b0, uint32_t b1) {
    asm volatile(
        "mma.sync.aligned.m16n8k16.row.col.f32.bf16.bf16.f32 "
        "{%0,%1,%2,%3}, {%4,%5,%6,%7}, {%8,%9}, {%0,%1,%2,%3};"
        : "+f"(d[0]), "+f"(d[1]), "+f"(d[2]), "+f"(d[3])
        : "r"(a[0]), "r"(a[1]), "r"(a[2]), "r"(a[3]), "r"(b0), "r"(b1));
}

// swizzled P-tile lds: row i (128B), byte-col twoj, XOR chunk swizzle vs (i&7)
__device__ __forceinline__ uint32_t ldsp(uint32_t base, int i, int twoj) {
    uint32_t addr = base + (uint32_t)(i * 128 + (twoj ^ ((i & 7) << 4)));
    uint32_t v;
    asm volatile("ld.shared.b32 %0, [%1];" : "=r"(v) : "r"(addr));
    return v;
}

// ---------------- K_prep ----------------
__global__ void k_prep(const float* __restrict__ pp, const float* __restrict__ ssrc,
                       const float* __restrict__ stgt, const float* __restrict__ skw) {
    int idx = blockIdx.x * 256 + threadIdx.x;
    if (idx < 128 * 512) {
        int f = idx >> 9, c = idx & 511;
        float v;
        if (c < 256) { int h = c >> 6, o = c & 63; v = pp[h * 128 * 64 + f * 64 + o]; }
        else         { int cc = c - 256;           v = skw[cc * 128 + f]; }
        g_W512[f * 512 + c] = v;
    }
    if (idx < 128 * 8) {
        int f = idx >> 3, c = idx & 7;
        int h = c & 3;
        const float* sc = (c < 4) ? ssrc : stgt;
        float acc = 0.f;
        #pragma unroll
        for (int o = 0; o < 64; ++o) acc += pp[h * 128 * 64 + f * 64 + o] * sc[h * 64 + o];
        g_Wab[f * 8 + c] = acc;
    }
    if (idx < NN * 4) g_den[idx] = 0.f;
}

// ---------------- K0b: NW = nodes @ W512 ----------------
__global__ void __launch_bounds__(256) k_gemm_nw(const float* __restrict__ nodes) {
    __shared__ float sN[32][128];
    __shared__ float sW[32][128];
    int t = threadIdx.x;
    int r0 = blockIdx.x * 32;
    int c0 = blockIdx.y * 128;
    #pragma unroll
    for (int k = 0; k < 16; ++k) {
        int e = t + k * 256; int kk = e & 127, rr = e >> 7;
        sN[rr][kk] = nodes[(r0 + rr) * 128 + kk];
    }
    float acc[4][4] = {};
    int rg = t >> 5, cg = t & 31;
    for (int kc = 0; kc < 4; ++kc) {
        __syncthreads();
        #pragma unroll
        for (int k = 0; k < 16; ++k) {
            int e = t + k * 256; int cc = e & 127, kk = e >> 7;
            sW[kk][cc] = g_W512[(kc * 32 + kk) * 512 + c0 + cc];
        }
        __syncthreads();
        #pragma unroll
        for (int k = 0; k < 32; ++k) {
            float4 b = *(const float4*)&sW[k][cg * 4];
            #pragma unroll
            for (int q = 0; q < 4; ++q) {
                float a = sN[rg * 4 + q][kc * 32 + k];
                acc[q][0] += a * b.x; acc[q][1] += a * b.y;
                acc[q][2] += a * b.z; acc[q][3] += a * b.w;
            }
        }
    }
    #pragma unroll
    for (int q = 0; q < 4; ++q) {
        *(float4*)&g_NW[(size_t)(r0 + rg * 4 + q) * 512 + c0 + cg * 4] =
            make_float4(acc[q][0], acc[q][1], acc[q][2], acc[q][3]);
    }
}

// ---------------- K0c ----------------
__global__ void k_ab(const float* __restrict__ nodes) {
    int idx = blockIdx.x * 256 + threadIdx.x;
    int n = idx >> 3, c = idx & 7;
    float acc = 0.f;
    #pragma unroll 8
    for (int f = 0; f < 128; ++f) acc += __ldg(&nodes[n * 128 + f]) * g_Wab[f * 8 + c];
    g_ab[idx] = acc;
}

// ---------------- K_A: mask + column denominators ----------------
__global__ void __launch_bounds__(256) k_passA(const float* __restrict__ deg,
                                               const float* __restrict__ bond,
                                               const float* __restrict__ cutp) {
    __shared__ float4 sa[64];
    int t = threadIdx.x;
    int j = blockIdx.x * 256 + t;
    int i0 = blockIdx.y * 64;
    float cut = cutp[0];
    float4 b4 = *(const float4*)&g_ab[j * 8 + 4];
    if (t < 64) sa[t] = *(const float4*)&g_ab[(i0 + t) * 8];
    __syncthreads();
    float d0 = 0.f, d1 = 0.f, d2 = 0.f, d3 = 0.f;
    #pragma unroll 4
    for (int il = 0; il < 64; ++il) {
        size_t off = (size_t)(i0 + il) * NN + j;
        float dd = deg[off], bb = bond[off];
        float wdm = dd + bb;
        float m = (wdm > 0.f) ? wdm : ((bb > cut) ? (bb + wdm) : NEG_INF);
        g_mask[off] = m;
        float4 a = sa[il];
        float x0 = a.x + b4.x; x0 = fmaxf(x0, 0.2f * x0); d0 += __expf(x0 + m);
        float x1 = a.y + b4.y; x1 = fmaxf(x1, 0.2f * x1); d1 += __expf(x1 + m);
        float x2 = a.z + b4.z; x2 = fmaxf(x2, 0.2f * x2); d2 += __expf(x2 + m);
        float x3 = a.w + b4.w; x3 = fmaxf(x3, 0.2f * x3); d3 += __expf(x3 + m);
    }
    atomicAdd(&g_den[j * 4 + 0], d0);
    atomicAdd(&g_den[j * 4 + 1], d1);
    atomicAdd(&g_den[j * 4 + 2], d2);
    atomicAdd(&g_den[j * 4 + 3], d3);
}

__global__ void k_inv() {
    int i = blockIdx.x * 256 + threadIdx.x;
    g_inv[i] = 1.0f / g_den[i];
}

// ---------------- K_T: split W^T into bf16 hi/lo:  W[hf][j] = NW[j][hf]*inv[j][h] ----------------
__global__ void __launch_bounds__(256) k_transp() {
    __shared__ float tile[32][33];
    int t = threadIdx.x;
    int j0 = blockIdx.x * 32, hf0 = blockIdx.y * 32;
    int col = t & 31, rq = t >> 5;
    #pragma unroll
    for (int q = 0; q < 4; ++q) {
        int jj = rq + q * 8;
        int hf = hf0 + col;
        tile[jj][col] = g_NW[(size_t)(j0 + jj) * 512 + hf] * g_inv[(j0 + jj) * 4 + (hf >> 6)];
    }
    __syncthreads();
    #pragma unroll
    for (int q = 0; q < 4; ++q) {
        int jj = rq + q * 8;
        float w = tile[col][jj];   // value at (hf0+jj, j0+col)
        uint32_t u = __float_as_uint(w);
        float lo = w - __uint_as_float(u & 0xffff0000u);
        size_t o = (size_t)(hf0 + jj) * NN + j0 + col;
        g_Whi[o] = (unsigned short)(u >> 16);
        unsigned short ls;
        {
            __nv_bfloat16 b = __float2bfloat16_rn(lo);
            ls = *(unsigned short*)&b;
        }
        g_Wlo[o] = ls;
    }
}

// ---------------- K_LN ----------------
__global__ void __launch_bounds__(256) k_ln(float* __restrict__ outln) {
    __shared__ float red[256];
    __shared__ float red2[256];
    int r = blockIdx.x, t = threadIdx.x;
    const float4* row = (const float4*)&g_mask[(size_t)r * NN];
    float4 v[4];
    float s = 0.f, sq = 0.f;
    #pragma unroll
    for (int k = 0; k < 4; ++k) {
        v[k] = row[t + k * 256];
        s  += v[k].x + v[k].y + v[k].z + v[k].w;
        sq += v[k].x * v[k].x + v[k].y * v[k].y + v[k].z * v[k].z + v[k].w * v[k].w;
    }
    red[t] = s; red2[t] = sq;
    __syncthreads();
    for (int off = 128; off > 0; off >>= 1) {
        if (t < off) { red[t] += red[t + off]; red2[t] += red2[t + off]; }
        __syncthreads();
    }
    float mu  = red[0] * (1.0f / NN);
    float var = red2[0] * (1.0f / NN) - mu * mu;
    float rstd = rsqrtf(var + 1e-5f);
    float4* o = (float4*)&outln[(size_t)r * NN];
    #pragma unroll
    for (int k = 0; k < 4; ++k) {
        float4 w = v[k];
        w.x = (w.x - mu) * rstd; w.y = (w.y - mu) * rstd;
        w.z = (w.z - mu) * rstd; w.w = (w.w - mu) * rstd;
        o[t + k * 256] = w;
    }
}

// ---------------- K_MMA: HMMA bf16x3 aggregation, full j reduction per CTA ----------------
// grid (64, 2): 64-row i-tile x head-group (2 heads). 8 warps:
//   wid = hg | fh<<1 | ih<<2 : head = by*2+hg, f-half fh*32, i-half ih*32. Warp tile 32i x 32f.
__global__ void __launch_bounds__(256) k_mma(float* __restrict__ out) {
    __shared__ char sP[4 * 8192];      // [head(2)][hi/lo] 64i x 64j bf16, swizzled
    __shared__ float sbv[2][64];       // b scores per head for chunk
    uint32_t smP = smem_u32(sP);

    int t = threadIdx.x;
    int l = t & 31;
    int wid = t >> 5;
    int hg = wid & 1, fh = (wid >> 1) & 1, ih = wid >> 2;
    int by = blockIdx.y;
    int head = by * 2 + hg;
    int i0 = blockIdx.x * 64;

    // staging role
    int iloc = t >> 2;             // 0..63
    int jq = (t & 3) * 16;         // 16 j per thread
    float2 aL = *(const float2*)&g_ab[(i0 + iloc) * 8 + by * 2];
    float aLv[2] = { aL.x, aL.y };

    float d[2][4][4] = {};         // [mt][nt][4]

    for (int ch = 0; ch < 64; ++ch) {
        int jb = ch * 64;
        __syncthreads();
        if (t < 128) {
            int hh = t >> 6, j = t & 63;
            sbv[hh][j] = g_ab[(jb + j) * 8 + 4 + by * 2 + hh];
        }
        __syncthreads();
        // ---- stage P (exp) hi/lo for both heads ----
        {
            float mv[16];
            const float4* mrow = (const float4*)&g_mask[(size_t)(i0 + iloc) * NN + jb + jq];
            #pragma unroll
            for (int q = 0; q < 4; ++q) *(float4*)&mv[q * 4] = mrow[q];
            #pragma unroll
            for (int hh = 0; hh < 2; ++hh) {
                float a = aLv[hh];
                uint32_t hpp[8], lpp[8];
                #pragma unroll
                for (int q = 0; q < 8; ++q) {
                    float2 b2 = *(const float2*)&sbv[hh][jq + q * 2];
                    float x0 = a + b2.x, x1 = a + b2.y;
                    x0 = fmaxf(x0, 0.2f * x0); x1 = fmaxf(x1, 0.2f * x1);
                    float e0 = (x0 + mv[q * 2]) * L2E;
                    float e1 = (x1 + mv[q * 2 + 1]) * L2E;
                    float p0, p1;
                    asm("ex2.approx.ftz.f32 %0, %1;" : "=f"(p0) : "f"(e0));
                    asm("ex2.approx.ftz.f32 %0, %1;" : "=f"(p1) : "f"(e1));
                    uint32_t u0 = __float_as_uint(p0), u1 = __float_as_uint(p1);
                    hpp[q] = __byte_perm(u0, u1, 0x7632);
                    float l0 = p0 - __uint_as_float(u0 & 0xffff0000u);
                    float l1 = p1 - __uint_as_float(u1 & 0xffff0000u);
                    asm("cvt.rn.bf16x2.f32 %0, %1, %2;" : "=r"(lpp[q]) : "f"(l1), "f"(l0));
                }
                uint32_t sw = (uint32_t)((iloc & 7) << 4);
                uint32_t o1 = (uint32_t)(iloc * 128) + ((uint32_t)(2 * jq) ^ sw);
                uint32_t o2 = (uint32_t)(iloc * 128) + ((uint32_t)(2 * jq + 16) ^ sw);
                char* Phi = sP + (hh * 2 + 0) * 8192;
                char* Plo = sP + (hh * 2 + 1) * 8192;
                *(uint4*)(Phi + o1) = make_uint4(hpp[0], hpp[1], hpp[2], hpp[3]);
                *(uint4*)(Phi + o2) = make_uint4(hpp[4], hpp[5], hpp[6], hpp[7]);
                *(uint4*)(Plo + o1) = make_uint4(lpp[0], lpp[1], lpp[2], lpp[3]);
                *(uint4*)(Plo + o2) = make_uint4(lpp[4], lpp[5], lpp[6], lpp[7]);
            }
        }
        __syncthreads();
        // ---- MMA phase ----
        uint32_t baseHi = smP + (uint32_t)((hg * 2 + 0) * 8192);
        uint32_t baseLo = smP + (uint32_t)((hg * 2 + 1) * 8192);
        #pragma unroll
        for (int kt = 0; kt < 4; ++kt) {
            int tj = kt * 32 + (l & 3) * 4;    // byte-col of first j pair
            uint32_t ahi[2][4], alo[2][4];
            #pragma unroll
            for (int mt = 0; mt < 2; ++mt) {
                int ib = ih * 32 + mt * 16 + (l >> 2);
                ahi[mt][0] = ldsp(baseHi, ib, tj);
                ahi[mt][1] = ldsp(baseHi, ib + 8, tj);
                ahi[mt][2] = ldsp(baseHi, ib, tj + 16);
                ahi[mt][3] = ldsp(baseHi, ib + 8, tj + 16);
                alo[mt][0] = ldsp(baseLo, ib, tj);
                alo[mt][1] = ldsp(baseLo, ib + 8, tj);
                alo[mt][2] = ldsp(baseLo, ib, tj + 16);
                alo[mt][3] = ldsp(baseLo, ib + 8, tj + 16);
            }
            #pragma unroll
            for (int nt = 0; nt < 4; ++nt) {
                int frow = head * 64 + fh * 32 + nt * 8 + (l >> 2);
                size_t wo = (size_t)frow * NN + jb + kt * 16 + (l & 3) * 2;
                uint32_t b0h = *(const uint32_t*)&g_Whi[wo];
                uint32_t b1h = *(const uint32_t*)&g_Whi[wo + 8];
                uint32_t b0l = *(const uint32_t*)&g_Wlo[wo];
                uint32_t b1l = *(const uint32_t*)&g_Wlo[wo + 8];
                #pragma unroll
                for (int mt = 0; mt < 2; ++mt) {
                    mma_bf16(d[mt][nt], ahi[mt], b0h, b1h);
                    mma_bf16(d[mt][nt], ahi[mt], b0l, b1l);
                    mma_bf16(d[mt][nt], alo[mt], b0h, b1h);
                }
            }
        }
    }

    // ---- epilogue: + skip, ELU, store ----
    #pragma unroll
    for (int mt = 0; mt < 2; ++mt) {
        #pragma unroll
        for (int nt = 0; nt < 4; ++nt) {
            int gcol = head * 64 + fh * 32 + nt * 8 + (l & 3) * 2;
            #pragma unroll
            for (int rr = 0; rr < 2; ++rr) {
                int row = i0 + ih * 32 + mt * 16 + (l >> 2) + rr * 8;
                float2 sk = *(const float2*)&g_NW[(size_t)row * 512 + 256 + gcol];
                float v0 = d[mt][nt][rr * 2 + 0] + sk.x;
                float v1 = d[mt][nt][rr * 2 + 1] + sk.y;
                v0 = (v0 > 0.f) ? v0 : expm1f(v0);
                v1 = (v1 > 0.f) ? v1 : expm1f(v1);
                *(float2*)&out[(size_t)row * 256 + gcol] = make_float2(v0, v1);
            }
        }
    }
}

// ---------------- launch ----------------
extern "C" void kernel_launch(void* const* d_in, const int* in_sizes, int n_in,
                              void* d_out, int out_size) {
    const float* nodes = (const float*)d_in[0];
    const float* deg   = (const float*)d_in[1];
    const float* bond  = (const float*)d_in[3];
    const float* pp    = (const float*)d_in[4];
    const float* ssrc  = (const float*)d_in[5];
    const float* stgt  = (const float*)d_in[6];
    const float* skw   = (const float*)d_in[7];
    const float* cutp  = (const float*)d_in[8];

    float* out = (float*)d_out;
    float* outln = out + (size_t)NN * 256;

    k_prep<<<256, 256>>>(pp, ssrc, stgt, skw);
    k_gemm_nw<<<dim3(128, 4), 256>>>(nodes);
    k_ab<<<128, 256>>>(nodes);
    k_passA<<<dim3(16, 64), 256>>>(deg, bond, cutp);
    k_inv<<<64, 256>>>();
    k_transp<<<dim3(128, 8), 256>>>();
    k_ln<<<NN, 256>>>(outln);
    k_mma<<<dim3(64, 2), 256>>>(out);
}

// round 7
// speedup vs baseline: 2.3903x; 1.5886x over previous
#include <cuda_runtime.h>
#include <cuda_bf16.h>
#include <math.h>
#include <stdint.h>

#define NN 4096
#define NEG_INF -1e9f
#define L2E 1.4426950408889634f

// ---------------- scratch (device globals; no allocation allowed) ----------------
__device__ __align__(16) float g_mask[(size_t)NN * NN];
__device__ __align__(16) float g_NW[(size_t)NN * 512];
__device__ __align__(16) unsigned short g_Whi[(size_t)256 * NN];
__device__ __align__(16) unsigned short g_Wlo[(size_t)256 * NN];
__device__ __align__(16) float g_ab[NN * 8];
__device__ __align__(16) float g_W512[128 * 512];
__device__ __align__(16) float g_Wab[128 * 8];
__device__ __align__(16) float g_den[NN * 4];
__device__ __align__(16) float g_inv[NN * 4];

__device__ __forceinline__ uint32_t smem_u32(const void* p) {
    uint32_t a;
    asm("{ .reg .u64 tmp; cvta.to.shared.u64 tmp, %1; cvt.u32.u64 %0, tmp; }" : "=r"(a) : "l"(p));
    return a;
}
__device__ __forceinline__ void mma_bf16(float* d, const uint32_t* a, uint32_t b0, uint32_t b1) {
    asm volatile(
        "mma.sync.aligned.m16n8k16.row.col.f32.bf16.bf16.f32 "
        "{%0,%1,%2,%3}, {%4,%5,%6,%7}, {%8,%9}, {%0,%1,%2,%3};"
        : "+f"(d[0]), "+f"(d[1]), "+f"(d[2]), "+f"(d[3])
        : "r"(a[0]), "r"(a[1]), "r"(a[2]), "r"(a[3]), "r"(b0), "r"(b1));
}
#define LDSM4(r, a) asm volatile("ldmatrix.sync.aligned.m8n8.x4.shared.b16 {%0,%1,%2,%3}, [%4];" \
    : "=r"((r)[0]), "=r"((r)[1]), "=r"((r)[2]), "=r"((r)[3]) : "r"(a))
__device__ __forceinline__ void cp_async16(uint32_t dst, const void* src) {
    asm volatile("cp.async.ca.shared.global [%0], [%1], 16;" :: "r"(dst), "l"(src));
}
#define CP_COMMIT()  asm volatile("cp.async.commit_group;" ::: "memory")
#define CP_WAIT(n)   asm volatile("cp.async.wait_group %0;" :: "n"(n) : "memory")

// ---------------- K_prep ----------------
__global__ void k_prep(const float* __restrict__ pp, const float* __restrict__ ssrc,
                       const float* __restrict__ stgt, const float* __restrict__ skw) {
    int idx = blockIdx.x * 256 + threadIdx.x;
    if (idx < 128 * 512) {
        int f = idx >> 9, c = idx & 511;
        float v;
        if (c < 256) { int h = c >> 6, o = c & 63; v = pp[h * 128 * 64 + f * 64 + o]; }
        else         { int cc = c - 256;           v = skw[cc * 128 + f]; }
        g_W512[f * 512 + c] = v;
    }
    if (idx < 128 * 8) {
        int f = idx >> 3, c = idx & 7;
        int h = c & 3;
        const float* sc = (c < 4) ? ssrc : stgt;
        float acc = 0.f;
        #pragma unroll
        for (int o = 0; o < 64; ++o) acc += pp[h * 128 * 64 + f * 64 + o] * sc[h * 64 + o];
        g_Wab[f * 8 + c] = acc;
    }
    if (idx < NN * 4) g_den[idx] = 0.f;
}

// ---------------- K0b: NW = nodes @ W512 ----------------
__global__ void __launch_bounds__(256) k_gemm_nw(const float* __restrict__ nodes) {
    __shared__ float sN[32][128];
    __shared__ float sW[32][128];
    int t = threadIdx.x;
    int r0 = blockIdx.x * 32;
    int c0 = blockIdx.y * 128;
    #pragma unroll
    for (int k = 0; k < 16; ++k) {
        int e = t + k * 256; int kk = e & 127, rr = e >> 7;
        sN[rr][kk] = nodes[(r0 + rr) * 128 + kk];
    }
    float acc[4][4] = {};
    int rg = t >> 5, cg = t & 31;
    for (int kc = 0; kc < 4; ++kc) {
        __syncthreads();
        #pragma unroll
        for (int k = 0; k < 16; ++k) {
            int e = t + k * 256; int cc = e & 127, kk = e >> 7;
            sW[kk][cc] = g_W512[(kc * 32 + kk) * 512 + c0 + cc];
        }
        __syncthreads();
        #pragma unroll
        for (int k = 0; k < 32; ++k) {
            float4 b = *(const float4*)&sW[k][cg * 4];
            #pragma unroll
            for (int q = 0; q < 4; ++q) {
                float a = sN[rg * 4 + q][kc * 32 + k];
                acc[q][0] += a * b.x; acc[q][1] += a * b.y;
                acc[q][2] += a * b.z; acc[q][3] += a * b.w;
            }
        }
    }
    #pragma unroll
    for (int q = 0; q < 4; ++q) {
        *(float4*)&g_NW[(size_t)(r0 + rg * 4 + q) * 512 + c0 + cg * 4] =
            make_float4(acc[q][0], acc[q][1], acc[q][2], acc[q][3]);
    }
}

// ---------------- K0c ----------------
__global__ void k_ab(const float* __restrict__ nodes) {
    int idx = blockIdx.x * 256 + threadIdx.x;
    int n = idx >> 3, c = idx & 7;
    float acc = 0.f;
    #pragma unroll 8
    for (int f = 0; f < 128; ++f) acc += __ldg(&nodes[n * 128 + f]) * g_Wab[f * 8 + c];
    g_ab[idx] = acc;
}

// ---------------- K_A: mask + column denominators (float4 vectorized) ----------------
__global__ void __launch_bounds__(256) k_passA(const float* __restrict__ deg,
                                               const float* __restrict__ bond,
                                               const float* __restrict__ cutp) {
    __shared__ float4 sa[64];
    int t = threadIdx.x;
    int j0 = blockIdx.x * 1024 + t * 4;
    int i0 = blockIdx.y * 64;
    float cut = cutp[0];
    float4 bq[4];
    #pragma unroll
    for (int q = 0; q < 4; ++q) bq[q] = *(const float4*)&g_ab[(j0 + q) * 8 + 4];
    if (t < 64) sa[t] = *(const float4*)&g_ab[(i0 + t) * 8];
    __syncthreads();
    float acc[16] = {};
    #pragma unroll 2
    for (int il = 0; il < 64; ++il) {
        size_t off = (size_t)(i0 + il) * NN + j0;
        float4 dd = *(const float4*)&deg[off];
        float4 bb = *(const float4*)&bond[off];
        float m[4];
        {
            float w0 = dd.x + bb.x; m[0] = (w0 > 0.f) ? w0 : ((bb.x > cut) ? (bb.x + w0) : NEG_INF);
            float w1 = dd.y + bb.y; m[1] = (w1 > 0.f) ? w1 : ((bb.y > cut) ? (bb.y + w1) : NEG_INF);
            float w2 = dd.z + bb.z; m[2] = (w2 > 0.f) ? w2 : ((bb.z > cut) ? (bb.z + w2) : NEG_INF);
            float w3 = dd.w + bb.w; m[3] = (w3 > 0.f) ? w3 : ((bb.w > cut) ? (bb.w + w3) : NEG_INF);
        }
        *(float4*)&g_mask[off] = make_float4(m[0], m[1], m[2], m[3]);
        float4 a = sa[il];
        #pragma unroll
        for (int q = 0; q < 4; ++q) {
            float x0 = a.x + bq[q].x; x0 = fmaxf(x0, 0.2f * x0); acc[q * 4 + 0] += __expf(x0 + m[q]);
            float x1 = a.y + bq[q].y; x1 = fmaxf(x1, 0.2f * x1); acc[q * 4 + 1] += __expf(x1 + m[q]);
            float x2 = a.z + bq[q].z; x2 = fmaxf(x2, 0.2f * x2); acc[q * 4 + 2] += __expf(x2 + m[q]);
            float x3 = a.w + bq[q].w; x3 = fmaxf(x3, 0.2f * x3); acc[q * 4 + 3] += __expf(x3 + m[q]);
        }
    }
    #pragma unroll
    for (int q = 0; q < 4; ++q) {
        #pragma unroll
        for (int h = 0; h < 4; ++h)
            atomicAdd(&g_den[(j0 + q) * 4 + h], acc[q * 4 + h]);
    }
}

__global__ void k_inv() {
    int i = blockIdx.x * 256 + threadIdx.x;
    g_inv[i] = 1.0f / g_den[i];
}

// ---------------- K_T: split W^T into bf16 hi/lo ----------------
__global__ void __launch_bounds__(256) k_transp() {
    __shared__ float tile[32][33];
    int t = threadIdx.x;
    int j0 = blockIdx.x * 32, hf0 = blockIdx.y * 32;
    int col = t & 31, rq = t >> 5;
    #pragma unroll
    for (int q = 0; q < 4; ++q) {
        int jj = rq + q * 8;
        int hf = hf0 + col;
        tile[jj][col] = g_NW[(size_t)(j0 + jj) * 512 + hf] * g_inv[(j0 + jj) * 4 + (hf >> 6)];
    }
    __syncthreads();
    #pragma unroll
    for (int q = 0; q < 4; ++q) {
        int jj = rq + q * 8;
        float w = tile[col][jj];
        uint32_t u = __float_as_uint(w);
        float lo = w - __uint_as_float(u & 0xffff0000u);
        size_t o = (size_t)(hf0 + jj) * NN + j0 + col;
        g_Whi[o] = (unsigned short)(u >> 16);
        __nv_bfloat16 b = __float2bfloat16_rn(lo);
        g_Wlo[o] = *(unsigned short*)&b;
    }
}

// ---------------- K_LN ----------------
__global__ void __launch_bounds__(256) k_ln(float* __restrict__ outln) {
    __shared__ float red[256];
    __shared__ float red2[256];
    int r = blockIdx.x, t = threadIdx.x;
    const float4* row = (const float4*)&g_mask[(size_t)r * NN];
    float4 v[4];
    float s = 0.f, sq = 0.f;
    #pragma unroll
    for (int k = 0; k < 4; ++k) {
        v[k] = row[t + k * 256];
        s  += v[k].x + v[k].y + v[k].z + v[k].w;
        sq += v[k].x * v[k].x + v[k].y * v[k].y + v[k].z * v[k].z + v[k].w * v[k].w;
    }
    red[t] = s; red2[t] = sq;
    __syncthreads();
    for (int off = 128; off > 0; off >>= 1) {
        if (t < off) { red[t] += red[t + off]; red2[t] += red2[t + off]; }
        __syncthreads();
    }
    float mu  = red[0] * (1.0f / NN);
    float var = red2[0] * (1.0f / NN) - mu * mu;
    float rstd = rsqrtf(var + 1e-5f);
    float4* o = (float4*)&outln[(size_t)r * NN];
    #pragma unroll
    for (int k = 0; k < 4; ++k) {
        float4 w = v[k];
        w.x = (w.x - mu) * rstd; w.y = (w.y - mu) * rstd;
        w.z = (w.z - mu) * rstd; w.w = (w.w - mu) * rstd;
        o[t + k * 256] = w;
    }
}

// ---------------- K_MMA: pipelined HMMA bf16x3 aggregation ----------------
// grid (64, 2): 64-row i-tile x head-group(2 heads). 8 warps: hg | fh<<1 | ih<<2.
// smem: sP 32KB (4 planes [hh][hi/lo] 64ix64j) | sW 2x32KB (cp.async double buf) | sbv 1KB
#define WBUF 32768
#define SMEM_MMA (32768 + 2 * WBUF + 1024)

__global__ void __launch_bounds__(256) k_mma(float* __restrict__ out) {
    extern __shared__ char sm[];
    char* sP = sm;
    float* sbv = (float*)(sm + 32768 + 2 * WBUF);   // [buf*2+hh][64]
    uint32_t smP = smem_u32(sm);
    uint32_t smW = smP + 32768;

    int t = threadIdx.x;
    int l = t & 31;
    int wid = t >> 5;
    int hg = wid & 1, fh = (wid >> 1) & 1, ih = wid >> 2;
    int by = blockIdx.y;
    int head = by * 2 + hg;
    int i0 = blockIdx.x * 64;

    // staging roles
    int iloc = t >> 2;             // 0..63
    int jq = (t & 3) * 16;
    float2 aLp = *(const float2*)&g_ab[(i0 + iloc) * 8 + by * 2];
    float aLv[2] = { aLp.x, aLp.y };

    // lane-constant LDSM address parts
    int lt = l >> 3, lr = l & 7;
    uint32_t swz = (uint32_t)(lr << 4);
    uint32_t aRow0 = (uint32_t)((ih * 32 + lr + (lt & 1) * 8) * 128);
    uint32_t aColT = (uint32_t)(16 * (lt >> 1));
    uint32_t bRow0 = (uint32_t)((hg * 64 + fh * 32 + (lt >> 1) * 8 + lr) * 128);
    uint32_t bColT = (uint32_t)(16 * (lt & 1));
    uint32_t pHi = smP + (uint32_t)(hg * 2 * 8192);
    uint32_t pLo = pHi + 8192;

    // W cp.async roles: r = t>>1 row (0..127), chunks c = (t&1)*4+q
    int wr = t >> 1;
    int wc0 = (t & 1) * 4;
    const unsigned short* whsrc = &g_Whi[(size_t)(by * 128 + wr) * NN];
    const unsigned short* wlsrc = &g_Wlo[(size_t)(by * 128 + wr) * NN];
    uint32_t wdstHi = smW + (uint32_t)(wr * 128);
    uint32_t wswz = (uint32_t)((wr & 7) << 4);

    float d[2][4][4] = {};
    float mv[16];

    // ---- prologue: mask ch0, sbv[0], W ch0 -> buf0 ----
    {
        const float4* mrow = (const float4*)&g_mask[(size_t)(i0 + iloc) * NN + jq];
        #pragma unroll
        for (int q = 0; q < 4; ++q) *(float4*)&mv[q * 4] = mrow[q];
        if (t < 128) {
            int hh = t >> 6, j = t & 63;
            sbv[hh * 64 + j] = g_ab[j * 8 + 4 + by * 2 + hh];
        }
        #pragma unroll
        for (int q = 0; q < 4; ++q) {
            int c = wc0 + q;
            uint32_t dsw = (uint32_t)(c * 16) ^ wswz;
            cp_async16(wdstHi + dsw, whsrc + c * 8);
            cp_async16(wdstHi + 16384 + dsw, wlsrc + c * 8);
        }
        CP_COMMIT();
        CP_WAIT(0);
        __syncthreads();
    }

    for (int ch = 0; ch < 64; ++ch) {
        int buf = ch & 1;
        int jb = ch * 64;
        // ---- stage P (exp, hi/lo bf16) ----
        {
            #pragma unroll
            for (int hh = 0; hh < 2; ++hh) {
                float a = aLv[hh];
                const float* bvec = &sbv[(buf * 2 + hh) * 64];
                uint32_t hpp[8], lpp[8];
                #pragma unroll
                for (int q = 0; q < 8; ++q) {
                    float2 b2 = *(const float2*)&bvec[jq + q * 2];
                    float x0 = a + b2.x, x1 = a + b2.y;
                    x0 = fmaxf(x0, 0.2f * x0); x1 = fmaxf(x1, 0.2f * x1);
                    float e0 = (x0 + mv[q * 2]) * L2E;
                    float e1 = (x1 + mv[q * 2 + 1]) * L2E;
                    float p0, p1;
                    asm("ex2.approx.ftz.f32 %0, %1;" : "=f"(p0) : "f"(e0));
                    asm("ex2.approx.ftz.f32 %0, %1;" : "=f"(p1) : "f"(e1));
                    uint32_t u0 = __float_as_uint(p0), u1 = __float_as_uint(p1);
                    hpp[q] = __byte_perm(u0, u1, 0x7632);
                    float l0 = p0 - __uint_as_float(u0 & 0xffff0000u);
                    float l1 = p1 - __uint_as_float(u1 & 0xffff0000u);
                    asm("cvt.rn.bf16x2.f32 %0, %1, %2;" : "=r"(lpp[q]) : "f"(l1), "f"(l0));
                }
                uint32_t sw = (uint32_t)((iloc & 7) << 4);
                uint32_t o1 = (uint32_t)(iloc * 128) + ((uint32_t)(2 * jq) ^ sw);
                uint32_t o2 = (uint32_t)(iloc * 128) + ((uint32_t)(2 * jq + 16) ^ sw);
                char* Phi = sP + (hh * 2 + 0) * 8192;
                char* Plo = sP + (hh * 2 + 1) * 8192;
                *(uint4*)(Phi + o1) = make_uint4(hpp[0], hpp[1], hpp[2], hpp[3]);
                *(uint4*)(Phi + o2) = make_uint4(hpp[4], hpp[5], hpp[6], hpp[7]);
                *(uint4*)(Plo + o1) = make_uint4(lpp[0], lpp[1], lpp[2], lpp[3]);
                *(uint4*)(Plo + o2) = make_uint4(lpp[4], lpp[5], lpp[6], lpp[7]);
            }
        }
        // ---- prefetch next chunk: mask regs, sbv, W (cp.async) ----
        if (ch < 63) {
            const float4* mrow = (const float4*)&g_mask[(size_t)(i0 + iloc) * NN + jb + 64 + jq];
            #pragma unroll
            for (int q = 0; q < 4; ++q) *(float4*)&mv[q * 4] = mrow[q];
            if (t < 128) {
                int hh = t >> 6, j = t & 63;
                sbv[((buf ^ 1) * 2 + hh) * 64 + j] = g_ab[(jb + 64 + j) * 8 + 4 + by * 2 + hh];
            }
            uint32_t wdst = wdstHi + (uint32_t)((buf ^ 1) * WBUF);
            const unsigned short* wh = whsrc + jb + 64;
            const unsigned short* wl = wlsrc + jb + 64;
            #pragma unroll
            for (int q = 0; q < 4; ++q) {
                int c = wc0 + q;
                uint32_t dsw = (uint32_t)(c * 16) ^ wswz;
                cp_async16(wdst + dsw, wh + c * 8);
                cp_async16(wdst + 16384 + dsw, wl + c * 8);
            }
        }
        CP_COMMIT();
        CP_WAIT(1);
        __syncthreads();
        // ---- MMA phase (LDSM fragments) ----
        uint32_t wbase = smW + (uint32_t)(buf * WBUF);
        #pragma unroll
        for (int kt = 0; kt < 4; ++kt) {
            uint32_t cA = ((uint32_t)(32 * kt) + aColT) ^ swz;
            uint32_t cB = ((uint32_t)(32 * kt) + bColT) ^ swz;
            uint32_t ahi0[4], ahi1[4], alo0[4], alo1[4];
            LDSM4(ahi0, pHi + aRow0 + cA);
            LDSM4(ahi1, pHi + aRow0 + 2048 + cA);
            LDSM4(alo0, pLo + aRow0 + cA);
            LDSM4(alo1, pLo + aRow0 + 2048 + cA);
            uint32_t bh0[4], bh1[4], bl0[4], bl1[4];
            LDSM4(bh0, wbase + bRow0 + cB);
            LDSM4(bh1, wbase + bRow0 + 2048 + cB);
            LDSM4(bl0, wbase + 16384 + bRow0 + cB);
            LDSM4(bl1, wbase + 16384 + bRow0 + 2048 + cB);
            #pragma unroll
            for (int nt = 0; nt < 4; ++nt) {
                const uint32_t* bh = (nt < 2) ? bh0 : bh1;
                const uint32_t* bl = (nt < 2) ? bl0 : bl1;
                uint32_t b0h = bh[(nt & 1) * 2], b1h = bh[(nt & 1) * 2 + 1];
                uint32_t b0l = bl[(nt & 1) * 2], b1l = bl[(nt & 1) * 2 + 1];
                mma_bf16(d[0][nt], ahi0, b0h, b1h);
                mma_bf16(d[1][nt], ahi1, b0h, b1h);
                mma_bf16(d[0][nt], ahi0, b0l, b1l);
                mma_bf16(d[1][nt], ahi1, b0l, b1l);
                mma_bf16(d[0][nt], alo0, b0h, b1h);
                mma_bf16(d[1][nt], alo1, b0h, b1h);
            }
        }
        __syncthreads();   // protect sP/sbv before next staging
    }

    // ---- epilogue: + skip, ELU, store ----
    #pragma unroll
    for (int mt = 0; mt < 2; ++mt) {
        #pragma unroll
        for (int nt = 0; nt < 4; ++nt) {
            int gcol = head * 64 + fh * 32 + nt * 8 + (l & 3) * 2;
            #pragma unroll
            for (int rr = 0; rr < 2; ++rr) {
                int row = i0 + ih * 32 + mt * 16 + (l >> 2) + rr * 8;
                float2 sk = *(const float2*)&g_NW[(size_t)row * 512 + 256 + gcol];
                float v0 = d[mt][nt][rr * 2 + 0] + sk.x;
                float v1 = d[mt][nt][rr * 2 + 1] + sk.y;
                v0 = (v0 > 0.f) ? v0 : expm1f(v0);
                v1 = (v1 > 0.f) ? v1 : expm1f(v1);
                *(float2*)&out[(size_t)row * 256 + gcol] = make_float2(v0, v1);
            }
        }
    }
}

// ---------------- launch ----------------
extern "C" void kernel_launch(void* const* d_in, const int* in_sizes, int n_in,
                              void* d_out, int out_size) {
    const float* nodes = (const float*)d_in[0];
    const float* deg   = (const float*)d_in[1];
    const float* bond  = (const float*)d_in[3];
    const float* pp    = (const float*)d_in[4];
    const float* ssrc  = (const float*)d_in[5];
    const float* stgt  = (const float*)d_in[6];
    const float* skw   = (const float*)d_in[7];
    const float* cutp  = (const float*)d_in[8];

    float* out = (float*)d_out;
    float* outln = out + (size_t)NN * 256;

    static int smem_set = 0;
    if (!smem_set) {
        cudaFuncSetAttribute(k_mma, cudaFuncAttributeMaxDynamicSharedMemorySize, SMEM_MMA);
        smem_set = 1;
    }

    k_prep<<<256, 256>>>(pp, ssrc, stgt, skw);
    k_gemm_nw<<<dim3(128, 4), 256>>>(nodes);
    k_ab<<<128, 256>>>(nodes);
    k_passA<<<dim3(4, 64), 256>>>(deg, bond, cutp);
    k_inv<<<64, 256>>>();
    k_transp<<<dim3(128, 8), 256>>>();
    k_ln<<<NN, 256>>>(outln);
    k_mma<<<dim3(64, 2), 256, SMEM_MMA>>>(out);
}

// round 8
// speedup vs baseline: 2.4250x; 1.0145x over previous
#include <cuda_runtime.h>
#include <cuda_bf16.h>
#include <math.h>
#include <stdint.h>

#define NN 4096
#define NEG_INF -1e9f
#define L2E 1.4426950408889634f

// ---------------- scratch ----------------
__device__ __align__(16) float g_mask[(size_t)NN * NN];
__device__ __align__(16) float g_NW[(size_t)NN * 512];
__device__ __align__(16) unsigned short g_Whi[(size_t)256 * NN];
__device__ __align__(16) unsigned short g_Wlo[(size_t)256 * NN];
__device__ __align__(16) float g_ab[NN * 8];
__device__ __align__(16) float g_W512[128 * 512];
__device__ __align__(16) float g_Wab[128 * 8];
__device__ __align__(16) float g_den[NN * 4];
__device__ __align__(16) float g_inv[NN * 4];
__device__ __align__(16) float g_part[2][(size_t)NN * 256];

__device__ __forceinline__ uint32_t smem_u32(const void* p) {
    uint32_t a;
    asm("{ .reg .u64 tmp; cvta.to.shared.u64 tmp, %1; cvt.u32.u64 %0, tmp; }" : "=r"(a) : "l"(p));
    return a;
}
__device__ __forceinline__ void mma_bf16(float* d, const uint32_t* a, uint32_t b0, uint32_t b1) {
    asm volatile(
        "mma.sync.aligned.m16n8k16.row.col.f32.bf16.bf16.f32 "
        "{%0,%1,%2,%3}, {%4,%5,%6,%7}, {%8,%9}, {%0,%1,%2,%3};"
        : "+f"(d[0]), "+f"(d[1]), "+f"(d[2]), "+f"(d[3])
        : "r"(a[0]), "r"(a[1]), "r"(a[2]), "r"(a[3]), "r"(b0), "r"(b1));
}
#define LDSM4(r, a) asm volatile("ldmatrix.sync.aligned.m8n8.x4.shared.b16 {%0,%1,%2,%3}, [%4];" \
    : "=r"((r)[0]), "=r"((r)[1]), "=r"((r)[2]), "=r"((r)[3]) : "r"(a))
__device__ __forceinline__ void cp_async16(uint32_t dst, const void* src) {
    asm volatile("cp.async.ca.shared.global [%0], [%1], 16;" :: "r"(dst), "l"(src));
}
#define CP_COMMIT()  asm volatile("cp.async.commit_group;" ::: "memory")
#define CP_WAIT(n)   asm volatile("cp.async.wait_group %0;" :: "n"(n) : "memory")

// ---------------- K_prep ----------------
__global__ void k_prep(const float* __restrict__ pp, const float* __restrict__ ssrc,
                       const float* __restrict__ stgt, const float* __restrict__ skw) {
    int idx = blockIdx.x * 256 + threadIdx.x;
    if (idx < 128 * 512) {
        int f = idx >> 9, c = idx & 511;
        float v;
        if (c < 256) { int h = c >> 6, o = c & 63; v = pp[h * 128 * 64 + f * 64 + o]; }
        else         { int cc = c - 256;           v = skw[cc * 128 + f]; }
        g_W512[f * 512 + c] = v;
    }
    if (idx < 128 * 8) {
        int f = idx >> 3, c = idx & 7;
        int h = c & 3;
        const float* sc = (c < 4) ? ssrc : stgt;
        float acc = 0.f;
        #pragma unroll
        for (int o = 0; o < 64; ++o) acc += pp[h * 128 * 64 + f * 64 + o] * sc[h * 64 + o];
        g_Wab[f * 8 + c] = acc;
    }
    if (idx < NN * 4) g_den[idx] = 0.f;
}

// ---------------- K0b: NW = nodes @ W512 ----------------
__global__ void __launch_bounds__(256) k_gemm_nw(const float* __restrict__ nodes) {
    __shared__ float sN[32][128];
    __shared__ float sW[32][128];
    int t = threadIdx.x;
    int r0 = blockIdx.x * 32;
    int c0 = blockIdx.y * 128;
    #pragma unroll
    for (int k = 0; k < 16; ++k) {
        int e = t + k * 256; int kk = e & 127, rr = e >> 7;
        sN[rr][kk] = nodes[(r0 + rr) * 128 + kk];
    }
    float acc[4][4] = {};
    int rg = t >> 5, cg = t & 31;
    for (int kc = 0; kc < 4; ++kc) {
        __syncthreads();
        #pragma unroll
        for (int k = 0; k < 16; ++k) {
            int e = t + k * 256; int cc = e & 127, kk = e >> 7;
            sW[kk][cc] = g_W512[(kc * 32 + kk) * 512 + c0 + cc];
        }
        __syncthreads();
        #pragma unroll
        for (int k = 0; k < 32; ++k) {
            float4 b = *(const float4*)&sW[k][cg * 4];
            #pragma unroll
            for (int q = 0; q < 4; ++q) {
                float a = sN[rg * 4 + q][kc * 32 + k];
                acc[q][0] += a * b.x; acc[q][1] += a * b.y;
                acc[q][2] += a * b.z; acc[q][3] += a * b.w;
            }
        }
    }
    #pragma unroll
    for (int q = 0; q < 4; ++q) {
        *(float4*)&g_NW[(size_t)(r0 + rg * 4 + q) * 512 + c0 + cg * 4] =
            make_float4(acc[q][0], acc[q][1], acc[q][2], acc[q][3]);
    }
}

// ---------------- K0c ----------------
__global__ void k_ab(const float* __restrict__ nodes) {
    int idx = blockIdx.x * 256 + threadIdx.x;
    int n = idx >> 3, c = idx & 7;
    float acc = 0.f;
    #pragma unroll 8
    for (int f = 0; f < 128; ++f) acc += __ldg(&nodes[n * 128 + f]) * g_Wab[f * 8 + c];
    g_ab[idx] = acc;
}

// ---------------- K_A: float4 vectorized, 512 CTAs ----------------
__global__ void __launch_bounds__(256) k_passA(const float* __restrict__ deg,
                                               const float* __restrict__ bond,
                                               const float* __restrict__ cutp) {
    __shared__ float4 sa[32];
    int t = threadIdx.x;
    int j0 = blockIdx.x * 1024 + t * 4;
    int i0 = blockIdx.y * 32;
    float cut = cutp[0];
    float4 bq[4];
    #pragma unroll
    for (int q = 0; q < 4; ++q) bq[q] = *(const float4*)&g_ab[(j0 + q) * 8 + 4];
    if (t < 32) sa[t] = *(const float4*)&g_ab[(i0 + t) * 8];
    __syncthreads();
    float acc[16] = {};
    #pragma unroll 2
    for (int il = 0; il < 32; ++il) {
        size_t off = (size_t)(i0 + il) * NN + j0;
        float4 dd = *(const float4*)&deg[off];
        float4 bb = *(const float4*)&bond[off];
        float m[4];
        {
            float w0 = dd.x + bb.x; m[0] = (w0 > 0.f) ? w0 : ((bb.x > cut) ? (bb.x + w0) : NEG_INF);
            float w1 = dd.y + bb.y; m[1] = (w1 > 0.f) ? w1 : ((bb.y > cut) ? (bb.y + w1) : NEG_INF);
            float w2 = dd.z + bb.z; m[2] = (w2 > 0.f) ? w2 : ((bb.z > cut) ? (bb.z + w2) : NEG_INF);
            float w3 = dd.w + bb.w; m[3] = (w3 > 0.f) ? w3 : ((bb.w > cut) ? (bb.w + w3) : NEG_INF);
        }
        *(float4*)&g_mask[off] = make_float4(m[0], m[1], m[2], m[3]);
        float4 a = sa[il];
        #pragma unroll
        for (int q = 0; q < 4; ++q) {
            float x0 = a.x + bq[q].x; x0 = fmaxf(x0, 0.2f * x0); acc[q * 4 + 0] += __expf(x0 + m[q]);
            float x1 = a.y + bq[q].y; x1 = fmaxf(x1, 0.2f * x1); acc[q * 4 + 1] += __expf(x1 + m[q]);
            float x2 = a.z + bq[q].z; x2 = fmaxf(x2, 0.2f * x2); acc[q * 4 + 2] += __expf(x2 + m[q]);
            float x3 = a.w + bq[q].w; x3 = fmaxf(x3, 0.2f * x3); acc[q * 4 + 3] += __expf(x3 + m[q]);
        }
    }
    #pragma unroll
    for (int q = 0; q < 4; ++q) {
        #pragma unroll
        for (int h = 0; h < 4; ++h)
            atomicAdd(&g_den[(j0 + q) * 4 + h], acc[q * 4 + h]);
    }
}

__global__ void k_inv() {
    int i = blockIdx.x * 256 + threadIdx.x;
    g_inv[i] = 1.0f / g_den[i];
}

// ---------------- K_T: split W^T into bf16 hi/lo ----------------
__global__ void __launch_bounds__(256) k_transp() {
    __shared__ float tile[32][33];
    int t = threadIdx.x;
    int j0 = blockIdx.x * 32, hf0 = blockIdx.y * 32;
    int col = t & 31, rq = t >> 5;
    #pragma unroll
    for (int q = 0; q < 4; ++q) {
        int jj = rq + q * 8;
        int hf = hf0 + col;
        tile[jj][col] = g_NW[(size_t)(j0 + jj) * 512 + hf] * g_inv[(j0 + jj) * 4 + (hf >> 6)];
    }
    __syncthreads();
    #pragma unroll
    for (int q = 0; q < 4; ++q) {
        int jj = rq + q * 8;
        float w = tile[col][jj];
        uint32_t u = __float_as_uint(w);
        float lo = w - __uint_as_float(u & 0xffff0000u);
        size_t o = (size_t)(hf0 + jj) * NN + j0 + col;
        g_Whi[o] = (unsigned short)(u >> 16);
        __nv_bfloat16 b = __float2bfloat16_rn(lo);
        g_Wlo[o] = *(unsigned short*)&b;
    }
}

// ---------------- K_LN ----------------
__global__ void __launch_bounds__(256) k_ln(float* __restrict__ outln) {
    __shared__ float red[256];
    __shared__ float red2[256];
    int r = blockIdx.x, t = threadIdx.x;
    const float4* row = (const float4*)&g_mask[(size_t)r * NN];
    float4 v[4];
    float s = 0.f, sq = 0.f;
    #pragma unroll
    for (int k = 0; k < 4; ++k) {
        v[k] = row[t + k * 256];
        s  += v[k].x + v[k].y + v[k].z + v[k].w;
        sq += v[k].x * v[k].x + v[k].y * v[k].y + v[k].z * v[k].z + v[k].w * v[k].w;
    }
    red[t] = s; red2[t] = sq;
    __syncthreads();
    for (int off = 128; off > 0; off >>= 1) {
        if (t < off) { red[t] += red[t + off]; red2[t] += red2[t + off]; }
        __syncthreads();
    }
    float mu  = red[0] * (1.0f / NN);
    float var = red2[0] * (1.0f / NN) - mu * mu;
    float rstd = rsqrtf(var + 1e-5f);
    float4* o = (float4*)&outln[(size_t)r * NN];
    #pragma unroll
    for (int k = 0; k < 4; ++k) {
        float4 w = v[k];
        w.x = (w.x - mu) * rstd; w.y = (w.y - mu) * rstd;
        w.z = (w.z - mu) * rstd; w.w = (w.w - mu) * rstd;
        o[t + k * 256] = w;
    }
}

// ---------------- K_MMA: pipelined HMMA bf16x3, grid (64 i, 4 head, 2 j-half) ----------------
// 8 warps: ih(4: 16 rows) x fh(2: 32 f). smem: sP 16KB | sW 2x16KB | sbv 512B = ~49KB
#define PBUF 16384
#define WBUF 16384
#define SMEM_MMA (PBUF + 2 * WBUF + 512)

__global__ void __launch_bounds__(256) k_mma(void) {
    extern __shared__ char sm[];
    char* sP = sm;                                   // hi 8KB | lo 8KB
    float* sbv = (float*)(sm + PBUF + 2 * WBUF);     // [buf][64]
    uint32_t smP = smem_u32(sm);
    uint32_t smW = smP + PBUF;

    int t = threadIdx.x;
    int l = t & 31;
    int wid = t >> 5;
    int fh = wid & 1, ih = wid >> 1;
    int head = blockIdx.y;
    int i0 = blockIdx.x * 64;
    int jz = blockIdx.z;
    int jstart = jz * 2048;

    // staging roles: P
    int iloc = t >> 2;             // 0..63
    int jq = (t & 3) * 16;
    float aL = g_ab[(i0 + iloc) * 8 + head];

    // LDSM lane-constant parts
    int lt = l >> 3, lr = l & 7;
    uint32_t swz = (uint32_t)(lr << 4);
    uint32_t aRow0 = (uint32_t)((ih * 16 + lr + (lt & 1) * 8) * 128);
    uint32_t aColT = (uint32_t)(16 * (lt >> 1));
    uint32_t bRow0 = (uint32_t)((fh * 32 + (lt >> 1) * 8 + lr) * 128);
    uint32_t bColT = (uint32_t)(16 * (lt & 1));
    uint32_t pHi = smP, pLo = smP + 8192;

    // W cp.async roles: wr = t>>2 (0..63), 2 chunks hi + 2 lo
    int wr = t >> 2;
    int wc0 = (t & 3) * 2;
    const unsigned short* whsrc = &g_Whi[(size_t)(head * 64 + wr) * NN + jstart];
    const unsigned short* wlsrc = &g_Wlo[(size_t)(head * 64 + wr) * NN + jstart];
    uint32_t wdstHi = smW + (uint32_t)(wr * 128);
    uint32_t wswz = (uint32_t)((wr & 7) << 4);

    float d[4][4] = {};
    float mv[16];

    // ---- prologue ----
    {
        const float4* mrow = (const float4*)&g_mask[(size_t)(i0 + iloc) * NN + jstart + jq];
        #pragma unroll
        for (int q = 0; q < 4; ++q) *(float4*)&mv[q * 4] = mrow[q];
        if (t < 64) sbv[t] = g_ab[(jstart + t) * 8 + 4 + head];
        #pragma unroll
        for (int q = 0; q < 2; ++q) {
            int c = wc0 + q;
            uint32_t dsw = (uint32_t)(c * 16) ^ wswz;
            cp_async16(wdstHi + dsw, whsrc + c * 8);
            cp_async16(wdstHi + 8192 + dsw, wlsrc + c * 8);
        }
        CP_COMMIT();
        CP_WAIT(0);
        __syncthreads();
    }

    for (int ch = 0; ch < 32; ++ch) {
        int buf = ch & 1;
        int jb = ch * 64;
        // ---- stage P (exp, hi/lo bf16) ----
        {
            const float* bvec = &sbv[buf * 64];
            uint32_t hpp[8], lpp[8];
            #pragma unroll
            for (int q = 0; q < 8; ++q) {
                float2 b2 = *(const float2*)&bvec[jq + q * 2];
                float x0 = aL + b2.x, x1 = aL + b2.y;
                x0 = fmaxf(x0, 0.2f * x0); x1 = fmaxf(x1, 0.2f * x1);
                float e0 = (x0 + mv[q * 2]) * L2E;
                float e1 = (x1 + mv[q * 2 + 1]) * L2E;
                float p0, p1;
                asm("ex2.approx.ftz.f32 %0, %1;" : "=f"(p0) : "f"(e0));
                asm("ex2.approx.ftz.f32 %0, %1;" : "=f"(p1) : "f"(e1));
                uint32_t u0 = __float_as_uint(p0), u1 = __float_as_uint(p1);
                hpp[q] = __byte_perm(u0, u1, 0x7632);
                float l0 = p0 - __uint_as_float(u0 & 0xffff0000u);
                float l1 = p1 - __uint_as_float(u1 & 0xffff0000u);
                asm("cvt.rn.bf16x2.f32 %0, %1, %2;" : "=r"(lpp[q]) : "f"(l1), "f"(l0));
            }
            uint32_t sw = (uint32_t)((iloc & 7) << 4);
            uint32_t o1 = (uint32_t)(iloc * 128) + ((uint32_t)(2 * jq) ^ sw);
            uint32_t o2 = (uint32_t)(iloc * 128) + ((uint32_t)(2 * jq + 16) ^ sw);
            *(uint4*)(sP + o1) = make_uint4(hpp[0], hpp[1], hpp[2], hpp[3]);
            *(uint4*)(sP + o2) = make_uint4(hpp[4], hpp[5], hpp[6], hpp[7]);
            *(uint4*)(sP + 8192 + o1) = make_uint4(lpp[0], lpp[1], lpp[2], lpp[3]);
            *(uint4*)(sP + 8192 + o2) = make_uint4(lpp[4], lpp[5], lpp[6], lpp[7]);
        }
        // ---- prefetch next chunk ----
        if (ch < 31) {
            const float4* mrow = (const float4*)&g_mask[(size_t)(i0 + iloc) * NN + jstart + jb + 64 + jq];
            #pragma unroll
            for (int q = 0; q < 4; ++q) *(float4*)&mv[q * 4] = mrow[q];
            if (t < 64) sbv[(buf ^ 1) * 64 + t] = g_ab[(jstart + jb + 64 + t) * 8 + 4 + head];
            uint32_t wdst = wdstHi + (uint32_t)((buf ^ 1) * WBUF);
            const unsigned short* wh = whsrc + jb + 64;
            const unsigned short* wl = wlsrc + jb + 64;
            #pragma unroll
            for (int q = 0; q < 2; ++q) {
                int c = wc0 + q;
                uint32_t dsw = (uint32_t)(c * 16) ^ wswz;
                cp_async16(wdst + dsw, wh + c * 8);
                cp_async16(wdst + 8192 + dsw, wl + c * 8);
            }
        }
        CP_COMMIT();
        CP_WAIT(1);
        __syncthreads();
        // ---- MMA (LDSM fragments) ----
        uint32_t wbase = smW + (uint32_t)(buf * WBUF);
        #pragma unroll
        for (int kt = 0; kt < 4; ++kt) {
            uint32_t cA = ((uint32_t)(32 * kt) + aColT) ^ swz;
            uint32_t cB = ((uint32_t)(32 * kt) + bColT) ^ swz;
            uint32_t ahi[4], alo[4];
            LDSM4(ahi, pHi + aRow0 + cA);
            LDSM4(alo, pLo + aRow0 + cA);
            uint32_t bh0[4], bh1[4], bl0[4], bl1[4];
            LDSM4(bh0, wbase + bRow0 + cB);
            LDSM4(bh1, wbase + bRow0 + 2048 + cB);
            LDSM4(bl0, wbase + 8192 + bRow0 + cB);
            LDSM4(bl1, wbase + 8192 + bRow0 + 2048 + cB);
            #pragma unroll
            for (int nt = 0; nt < 4; ++nt) {
                const uint32_t* bh = (nt < 2) ? bh0 : bh1;
                const uint32_t* bl = (nt < 2) ? bl0 : bl1;
                uint32_t b0h = bh[(nt & 1) * 2], b1h = bh[(nt & 1) * 2 + 1];
                uint32_t b0l = bl[(nt & 1) * 2], b1l = bl[(nt & 1) * 2 + 1];
                mma_bf16(d[nt], ahi, b0h, b1h);
                mma_bf16(d[nt], ahi, b0l, b1l);
                mma_bf16(d[nt], alo, b0h, b1h);
            }
        }
        __syncthreads();
    }

    // ---- write partials ----
    #pragma unroll
    for (int nt = 0; nt < 4; ++nt) {
        int gcol = head * 64 + fh * 32 + nt * 8 + (l & 3) * 2;
        #pragma unroll
        for (int rr = 0; rr < 2; ++rr) {
            int row = i0 + ih * 16 + (l >> 2) + rr * 8;
            *(float2*)&g_part[jz][(size_t)row * 256 + gcol] =
                make_float2(d[nt][rr * 2 + 0], d[nt][rr * 2 + 1]);
        }
    }
}

// ---------------- K_EPI: out = elu(part0 + part1 + skip) ----------------
__global__ void __launch_bounds__(256) k_epi(float* __restrict__ out) {
    int id4 = blockIdx.x * 256 + threadIdx.x;
    int row = id4 >> 6;
    int c0 = (id4 & 63) * 4;
    float4 s0 = *(const float4*)&g_part[0][(size_t)row * 256 + c0];
    float4 s1 = *(const float4*)&g_part[1][(size_t)row * 256 + c0];
    float4 sk = *(const float4*)&g_NW[(size_t)row * 512 + 256 + c0];
    float v0 = s0.x + s1.x + sk.x;
    float v1 = s0.y + s1.y + sk.y;
    float v2 = s0.z + s1.z + sk.z;
    float v3 = s0.w + s1.w + sk.w;
    v0 = (v0 > 0.f) ? v0 : expm1f(v0);
    v1 = (v1 > 0.f) ? v1 : expm1f(v1);
    v2 = (v2 > 0.f) ? v2 : expm1f(v2);
    v3 = (v3 > 0.f) ? v3 : expm1f(v3);
    *(float4*)&out[(size_t)row * 256 + c0] = make_float4(v0, v1, v2, v3);
}

// ---------------- launch ----------------
extern "C" void kernel_launch(void* const* d_in, const int* in_sizes, int n_in,
                              void* d_out, int out_size) {
    const float* nodes = (const float*)d_in[0];
    const float* deg   = (const float*)d_in[1];
    const float* bond  = (const float*)d_in[3];
    const float* pp    = (const float*)d_in[4];
    const float* ssrc  = (const float*)d_in[5];
    const float* stgt  = (const float*)d_in[6];
    const float* skw   = (const float*)d_in[7];
    const float* cutp  = (const float*)d_in[8];

    float* out = (float*)d_out;
    float* outln = out + (size_t)NN * 256;

    static int smem_set = 0;
    if (!smem_set) {
        cudaFuncSetAttribute(k_mma, cudaFuncAttributeMaxDynamicSharedMemorySize, SMEM_MMA);
        smem_set = 1;
    }

    k_prep<<<256, 256>>>(pp, ssrc, stgt, skw);
    k_gemm_nw<<<dim3(128, 4), 256>>>(nodes);
    k_ab<<<128, 256>>>(nodes);
    k_passA<<<dim3(4, 128), 256>>>(deg, bond, cutp);
    k_inv<<<64, 256>>>();
    k_transp<<<dim3(128, 8), 256>>>();
    k_ln<<<NN, 256>>>(outln);
    k_mma<<<dim3(64, 4, 2), 256, SMEM_MMA>>>();
    k_epi<<<1024, 256>>>(out);
}

// round 9
// speedup vs baseline: 2.5230x; 1.0404x over previous
#include <cuda_runtime.h>
#include <cuda_bf16.h>
#include <math.h>
#include <stdint.h>

#define NN 4096
#define NEG_INF -1e9f
#define L2E 1.4426950408889634f

// ---------------- scratch ----------------
__device__ __align__(16) float g_mask[(size_t)NN * NN];
__device__ __align__(16) float g_NW[(size_t)NN * 512];
__device__ __align__(16) unsigned short g_Whi[(size_t)256 * NN];   // bf16 rn(W^T * inv)
__device__ __align__(16) float g_ab[NN * 8];
__device__ __align__(16) float g_W512[128 * 512];
__device__ __align__(16) float g_Wab[128 * 8];
__device__ __align__(16) float g_den[NN * 4];
__device__ __align__(16) float g_inv[NN * 4];
__device__ __align__(16) float g_part[2][(size_t)NN * 256];

__device__ __forceinline__ uint32_t smem_u32(const void* p) {
    uint32_t a;
    asm("{ .reg .u64 tmp; cvta.to.shared.u64 tmp, %1; cvt.u32.u64 %0, tmp; }" : "=r"(a) : "l"(p));
    return a;
}
__device__ __forceinline__ void mma_bf16(float* d, const uint32_t* a, uint32_t b0, uint32_t b1) {
    asm volatile(
        "mma.sync.aligned.m16n8k16.row.col.f32.bf16.bf16.f32 "
        "{%0,%1,%2,%3}, {%4,%5,%6,%7}, {%8,%9}, {%0,%1,%2,%3};"
        : "+f"(d[0]), "+f"(d[1]), "+f"(d[2]), "+f"(d[3])
        : "r"(a[0]), "r"(a[1]), "r"(a[2]), "r"(a[3]), "r"(b0), "r"(b1));
}
#define LDSM4(r, a) asm volatile("ldmatrix.sync.aligned.m8n8.x4.shared.b16 {%0,%1,%2,%3}, [%4];" \
    : "=r"((r)[0]), "=r"((r)[1]), "=r"((r)[2]), "=r"((r)[3]) : "r"(a))
__device__ __forceinline__ void cp_async16(uint32_t dst, const void* src) {
    asm volatile("cp.async.ca.shared.global [%0], [%1], 16;" :: "r"(dst), "l"(src));
}
#define CP_COMMIT()  asm volatile("cp.async.commit_group;" ::: "memory")
#define CP_WAIT(n)   asm volatile("cp.async.wait_group %0;" :: "n"(n) : "memory")

// ---------------- K_prep ----------------
__global__ void k_prep(const float* __restrict__ pp, const float* __restrict__ ssrc,
                       const float* __restrict__ stgt, const float* __restrict__ skw) {
    int idx = blockIdx.x * 256 + threadIdx.x;
    if (idx < 128 * 512) {
        int f = idx >> 9, c = idx & 511;
        float v;
        if (c < 256) { int h = c >> 6, o = c & 63; v = pp[h * 128 * 64 + f * 64 + o]; }
        else         { int cc = c - 256;           v = skw[cc * 128 + f]; }
        g_W512[f * 512 + c] = v;
    }
    if (idx < 128 * 8) {
        int f = idx >> 3, c = idx & 7;
        int h = c & 3;
        const float* sc = (c < 4) ? ssrc : stgt;
        float acc = 0.f;
        #pragma unroll
        for (int o = 0; o < 64; ++o) acc += pp[h * 128 * 64 + f * 64 + o] * sc[h * 64 + o];
        g_Wab[f * 8 + c] = acc;
    }
    if (idx < NN * 4) g_den[idx] = 0.f;
}

// ---------------- K0b: NW = nodes @ W512 ----------------
__global__ void __launch_bounds__(256) k_gemm_nw(const float* __restrict__ nodes) {
    __shared__ float sN[32][128];
    __shared__ float sW[32][128];
    int t = threadIdx.x;
    int r0 = blockIdx.x * 32;
    int c0 = blockIdx.y * 128;
    #pragma unroll
    for (int k = 0; k < 16; ++k) {
        int e = t + k * 256; int kk = e & 127, rr = e >> 7;
        sN[rr][kk] = nodes[(r0 + rr) * 128 + kk];
    }
    float acc[4][4] = {};
    int rg = t >> 5, cg = t & 31;
    for (int kc = 0; kc < 4; ++kc) {
        __syncthreads();
        #pragma unroll
        for (int k = 0; k < 16; ++k) {
            int e = t + k * 256; int cc = e & 127, kk = e >> 7;
            sW[kk][cc] = g_W512[(kc * 32 + kk) * 512 + c0 + cc];
        }
        __syncthreads();
        #pragma unroll
        for (int k = 0; k < 32; ++k) {
            float4 b = *(const float4*)&sW[k][cg * 4];
            #pragma unroll
            for (int q = 0; q < 4; ++q) {
                float a = sN[rg * 4 + q][kc * 32 + k];
                acc[q][0] += a * b.x; acc[q][1] += a * b.y;
                acc[q][2] += a * b.z; acc[q][3] += a * b.w;
            }
        }
    }
    #pragma unroll
    for (int q = 0; q < 4; ++q) {
        *(float4*)&g_NW[(size_t)(r0 + rg * 4 + q) * 512 + c0 + cg * 4] =
            make_float4(acc[q][0], acc[q][1], acc[q][2], acc[q][3]);
    }
}

// ---------------- K0c ----------------
__global__ void k_ab(const float* __restrict__ nodes) {
    int idx = blockIdx.x * 256 + threadIdx.x;
    int n = idx >> 3, c = idx & 7;
    float acc = 0.f;
    #pragma unroll 8
    for (int f = 0; f < 128; ++f) acc += __ldg(&nodes[n * 128 + f]) * g_Wab[f * 8 + c];
    g_ab[idx] = acc;
}

// ---------------- K_A: float4 vectorized, 1024 CTAs (16 rows each) ----------------
__global__ void __launch_bounds__(256) k_passA(const float* __restrict__ deg,
                                               const float* __restrict__ bond,
                                               const float* __restrict__ cutp) {
    __shared__ float4 sa[16];
    int t = threadIdx.x;
    int j0 = blockIdx.x * 1024 + t * 4;
    int i0 = blockIdx.y * 16;
    float cut = cutp[0];
    float4 bq[4];
    #pragma unroll
    for (int q = 0; q < 4; ++q) bq[q] = *(const float4*)&g_ab[(j0 + q) * 8 + 4];
    if (t < 16) sa[t] = *(const float4*)&g_ab[(i0 + t) * 8];
    __syncthreads();
    float acc[16] = {};
    #pragma unroll 2
    for (int il = 0; il < 16; ++il) {
        size_t off = (size_t)(i0 + il) * NN + j0;
        float4 dd = *(const float4*)&deg[off];
        float4 bb = *(const float4*)&bond[off];
        float m[4];
        {
            float w0 = dd.x + bb.x; m[0] = (w0 > 0.f) ? w0 : ((bb.x > cut) ? (bb.x + w0) : NEG_INF);
            float w1 = dd.y + bb.y; m[1] = (w1 > 0.f) ? w1 : ((bb.y > cut) ? (bb.y + w1) : NEG_INF);
            float w2 = dd.z + bb.z; m[2] = (w2 > 0.f) ? w2 : ((bb.z > cut) ? (bb.z + w2) : NEG_INF);
            float w3 = dd.w + bb.w; m[3] = (w3 > 0.f) ? w3 : ((bb.w > cut) ? (bb.w + w3) : NEG_INF);
        }
        *(float4*)&g_mask[off] = make_float4(m[0], m[1], m[2], m[3]);
        float4 a = sa[il];
        #pragma unroll
        for (int q = 0; q < 4; ++q) {
            float x0 = a.x + bq[q].x; x0 = fmaxf(x0, 0.2f * x0); acc[q * 4 + 0] += __expf(x0 + m[q]);
            float x1 = a.y + bq[q].y; x1 = fmaxf(x1, 0.2f * x1); acc[q * 4 + 1] += __expf(x1 + m[q]);
            float x2 = a.z + bq[q].z; x2 = fmaxf(x2, 0.2f * x2); acc[q * 4 + 2] += __expf(x2 + m[q]);
            float x3 = a.w + bq[q].w; x3 = fmaxf(x3, 0.2f * x3); acc[q * 4 + 3] += __expf(x3 + m[q]);
        }
    }
    #pragma unroll
    for (int q = 0; q < 4; ++q) {
        #pragma unroll
        for (int h = 0; h < 4; ++h)
            atomicAdd(&g_den[(j0 + q) * 4 + h], acc[q * 4 + h]);
    }
}

__global__ void k_inv() {
    int i = blockIdx.x * 256 + threadIdx.x;
    g_inv[i] = 1.0f / g_den[i];
}

// ---------------- K_T: W^T[hf][j] = rn_bf16(NW[j][hf] * inv[j][h]) ----------------
__global__ void __launch_bounds__(256) k_transp() {
    __shared__ float tile[32][33];
    int t = threadIdx.x;
    int j0 = blockIdx.x * 32, hf0 = blockIdx.y * 32;
    int col = t & 31, rq = t >> 5;
    #pragma unroll
    for (int q = 0; q < 4; ++q) {
        int jj = rq + q * 8;
        int hf = hf0 + col;
        tile[jj][col] = g_NW[(size_t)(j0 + jj) * 512 + hf] * g_inv[(j0 + jj) * 4 + (hf >> 6)];
    }
    __syncthreads();
    #pragma unroll
    for (int q = 0; q < 4; ++q) {
        int jj = rq + q * 8;
        float w = tile[col][jj];
        __nv_bfloat16 b = __float2bfloat16_rn(w);
        g_Whi[(size_t)(hf0 + jj) * NN + j0 + col] = *(unsigned short*)&b;
    }
}

// ---------------- K_LN ----------------
__global__ void __launch_bounds__(256) k_ln(float* __restrict__ outln) {
    __shared__ float red[256];
    __shared__ float red2[256];
    int r = blockIdx.x, t = threadIdx.x;
    const float4* row = (const float4*)&g_mask[(size_t)r * NN];
    float4 v[4];
    float s = 0.f, sq = 0.f;
    #pragma unroll
    for (int k = 0; k < 4; ++k) {
        v[k] = row[t + k * 256];
        s  += v[k].x + v[k].y + v[k].z + v[k].w;
        sq += v[k].x * v[k].x + v[k].y * v[k].y + v[k].z * v[k].z + v[k].w * v[k].w;
    }
    red[t] = s; red2[t] = sq;
    __syncthreads();
    for (int off = 128; off > 0; off >>= 1) {
        if (t < off) { red[t] += red[t + off]; red2[t] += red2[t + off]; }
        __syncthreads();
    }
    float mu  = red[0] * (1.0f / NN);
    float var = red2[0] * (1.0f / NN) - mu * mu;
    float rstd = rsqrtf(var + 1e-5f);
    float4* o = (float4*)&outln[(size_t)r * NN];
    #pragma unroll
    for (int k = 0; k < 4; ++k) {
        float4 w = v[k];
        w.x = (w.x - mu) * rstd; w.y = (w.y - mu) * rstd;
        w.z = (w.z - mu) * rstd; w.w = (w.w - mu) * rstd;
        o[t + k * 256] = w;
    }
}

// ---------------- K_MMA: pipelined HMMA bf16x2 (P split, W rn) ----------------
// grid (64 i, 4 head, 2 j-half). 8 warps: fh(2: 32 f) x ih(4: 16 rows).
// smem: sP 16KB (hi 8K | lo 8K) | sW 2x8KB (cp.async double buf) | sbv 512B
#define PBUF 16384
#define WBUF 8192
#define SMEM_MMA (PBUF + 2 * WBUF + 512)

__global__ void __launch_bounds__(256) k_mma(void) {
    extern __shared__ char sm[];
    char* sP = sm;                                   // hi 8KB | lo 8KB
    float* sbv = (float*)(sm + PBUF + 2 * WBUF);     // [buf][64]
    uint32_t smP = smem_u32(sm);
    uint32_t smW = smP + PBUF;

    int t = threadIdx.x;
    int l = t & 31;
    int wid = t >> 5;
    int fh = wid & 1, ih = wid >> 1;
    int head = blockIdx.y;
    int i0 = blockIdx.x * 64;
    int jz = blockIdx.z;
    int jstart = jz * 2048;

    // staging roles: P
    int iloc = t >> 2;             // 0..63
    int jq = (t & 3) * 16;
    float aL = g_ab[(i0 + iloc) * 8 + head];

    // LDSM lane-constant parts
    int lt = l >> 3, lr = l & 7;
    uint32_t swz = (uint32_t)(lr << 4);
    uint32_t aRow0 = (uint32_t)((ih * 16 + lr + (lt & 1) * 8) * 128);
    uint32_t aColT = (uint32_t)(16 * (lt >> 1));
    uint32_t bRow0 = (uint32_t)((fh * 32 + (lt >> 1) * 8 + lr) * 128);
    uint32_t bColT = (uint32_t)(16 * (lt & 1));
    uint32_t pHi = smP, pLo = smP + 8192;

    // W cp.async roles: wr = t>>2 row (0..63), 2 x 16B chunks of the 128B row
    int wr = t >> 2;
    int wc0 = (t & 3) * 2;
    const unsigned short* whsrc = &g_Whi[(size_t)(head * 64 + wr) * NN + jstart];
    uint32_t wdstHi = smW + (uint32_t)(wr * 128);
    uint32_t wswz = (uint32_t)((wr & 7) << 4);

    float d[4][4] = {};
    float mv[16];

    // ---- prologue ----
    {
        const float4* mrow = (const float4*)&g_mask[(size_t)(i0 + iloc) * NN + jstart + jq];
        #pragma unroll
        for (int q = 0; q < 4; ++q) *(float4*)&mv[q * 4] = mrow[q];
        if (t < 64) sbv[t] = g_ab[(jstart + t) * 8 + 4 + head];
        #pragma unroll
        for (int q = 0; q < 2; ++q) {
            int c = wc0 + q;
            uint32_t dsw = (uint32_t)(c * 16) ^ wswz;
            cp_async16(wdstHi + dsw, whsrc + c * 8);
        }
        CP_COMMIT();
        CP_WAIT(0);
        __syncthreads();
    }

    for (int ch = 0; ch < 32; ++ch) {
        int buf = ch & 1;
        int jb = ch * 64;
        // ---- stage P (exp, hi trunc + lo rn bf16) ----
        {
            const float* bvec = &sbv[buf * 64];
            uint32_t hpp[8], lpp[8];
            #pragma unroll
            for (int q = 0; q < 8; ++q) {
                float2 b2 = *(const float2*)&bvec[jq + q * 2];
                float x0 = aL + b2.x, x1 = aL + b2.y;
                x0 = fmaxf(x0, 0.2f * x0); x1 = fmaxf(x1, 0.2f * x1);
                float e0 = (x0 + mv[q * 2]) * L2E;
                float e1 = (x1 + mv[q * 2 + 1]) * L2E;
                float p0, p1;
                asm("ex2.approx.ftz.f32 %0, %1;" : "=f"(p0) : "f"(e0));
                asm("ex2.approx.ftz.f32 %0, %1;" : "=f"(p1) : "f"(e1));
                uint32_t u0 = __float_as_uint(p0), u1 = __float_as_uint(p1);
                hpp[q] = __byte_perm(u0, u1, 0x7632);
                float l0 = p0 - __uint_as_float(u0 & 0xffff0000u);
                float l1 = p1 - __uint_as_float(u1 & 0xffff0000u);
                asm("cvt.rn.bf16x2.f32 %0, %1, %2;" : "=r"(lpp[q]) : "f"(l1), "f"(l0));
            }
            uint32_t sw = (uint32_t)((iloc & 7) << 4);
            uint32_t o1 = (uint32_t)(iloc * 128) + ((uint32_t)(2 * jq) ^ sw);
            uint32_t o2 = (uint32_t)(iloc * 128) + ((uint32_t)(2 * jq + 16) ^ sw);
            *(uint4*)(sP + o1) = make_uint4(hpp[0], hpp[1], hpp[2], hpp[3]);
            *(uint4*)(sP + o2) = make_uint4(hpp[4], hpp[5], hpp[6], hpp[7]);
            *(uint4*)(sP + 8192 + o1) = make_uint4(lpp[0], lpp[1], lpp[2], lpp[3]);
            *(uint4*)(sP + 8192 + o2) = make_uint4(lpp[4], lpp[5], lpp[6], lpp[7]);
        }
        // ---- prefetch next chunk ----
        if (ch < 31) {
            const float4* mrow = (const float4*)&g_mask[(size_t)(i0 + iloc) * NN + jstart + jb + 64 + jq];
            #pragma unroll
            for (int q = 0; q < 4; ++q) *(float4*)&mv[q * 4] = mrow[q];
            if (t < 64) sbv[(buf ^ 1) * 64 + t] = g_ab[(jstart + jb + 64 + t) * 8 + 4 + head];
            uint32_t wdst = wdstHi + (uint32_t)((buf ^ 1) * WBUF);
            const unsigned short* wh = whsrc + jb + 64;
            #pragma unroll
            for (int q = 0; q < 2; ++q) {
                int c = wc0 + q;
                uint32_t dsw = (uint32_t)(c * 16) ^ wswz;
                cp_async16(wdst + dsw, wh + c * 8);
            }
        }
        CP_COMMIT();
        CP_WAIT(1);
        __syncthreads();
        // ---- MMA (LDSM fragments): D += Phi*W + Plo*W ----
        uint32_t wbase = smW + (uint32_t)(buf * WBUF);
        #pragma unroll
        for (int kt = 0; kt < 4; ++kt) {
            uint32_t cA = ((uint32_t)(32 * kt) + aColT) ^ swz;
            uint32_t cB = ((uint32_t)(32 * kt) + bColT) ^ swz;
            uint32_t ahi[4], alo[4];
            LDSM4(ahi, pHi + aRow0 + cA);
            LDSM4(alo, pLo + aRow0 + cA);
            uint32_t bh0[4], bh1[4];
            LDSM4(bh0, wbase + bRow0 + cB);
            LDSM4(bh1, wbase + bRow0 + 2048 + cB);
            #pragma unroll
            for (int nt = 0; nt < 4; ++nt) {
                const uint32_t* bh = (nt < 2) ? bh0 : bh1;
                uint32_t b0h = bh[(nt & 1) * 2], b1h = bh[(nt & 1) * 2 + 1];
                mma_bf16(d[nt], ahi, b0h, b1h);
                mma_bf16(d[nt], alo, b0h, b1h);
            }
        }
        __syncthreads();
    }

    // ---- write partials ----
    #pragma unroll
    for (int nt = 0; nt < 4; ++nt) {
        int gcol = head * 64 + fh * 32 + nt * 8 + (l & 3) * 2;
        #pragma unroll
        for (int rr = 0; rr < 2; ++rr) {
            int row = i0 + ih * 16 + (l >> 2) + rr * 8;
            *(float2*)&g_part[jz][(size_t)row * 256 + gcol] =
                make_float2(d[nt][rr * 2 + 0], d[nt][rr * 2 + 1]);
        }
    }
}

// ---------------- K_EPI: out = elu(part0 + part1 + skip) ----------------
__global__ void __launch_bounds__(256) k_epi(float* __restrict__ out) {
    int id4 = blockIdx.x * 256 + threadIdx.x;
    int row = id4 >> 6;
    int c0 = (id4 & 63) * 4;
    float4 s0 = *(const float4*)&g_part[0][(size_t)row * 256 + c0];
    float4 s1 = *(const float4*)&g_part[1][(size_t)row * 256 + c0];
    float4 sk = *(const float4*)&g_NW[(size_t)row * 512 + 256 + c0];
    float v0 = s0.x + s1.x + sk.x;
    float v1 = s0.y + s1.y + sk.y;
    float v2 = s0.z + s1.z + sk.z;
    float v3 = s0.w + s1.w + sk.w;
    v0 = (v0 > 0.f) ? v0 : expm1f(v0);
    v1 = (v1 > 0.f) ? v1 : expm1f(v1);
    v2 = (v2 > 0.f) ? v2 : expm1f(v2);
    v3 = (v3 > 0.f) ? v3 : expm1f(v3);
    *(float4*)&out[(size_t)row * 256 + c0] = make_float4(v0, v1, v2, v3);
}

// ---------------- launch ----------------
extern "C" void kernel_launch(void* const* d_in, const int* in_sizes, int n_in,
                              void* d_out, int out_size) {
    const float* nodes = (const float*)d_in[0];
    const float* deg   = (const float*)d_in[1];
    const float* bond  = (const float*)d_in[3];
    const float* pp    = (const float*)d_in[4];
    const float* ssrc  = (const float*)d_in[5];
    const float* stgt  = (const float*)d_in[6];
    const float* skw   = (const float*)d_in[7];
    const float* cutp  = (const float*)d_in[8];

    float* out = (float*)d_out;
    float* outln = out + (size_t)NN * 256;

    static int smem_set = 0;
    if (!smem_set) {
        cudaFuncSetAttribute(k_mma, cudaFuncAttributeMaxDynamicSharedMemorySize, SMEM_MMA);
        smem_set = 1;
    }

    k_prep<<<256, 256>>>(pp, ssrc, stgt, skw);
    k_gemm_nw<<<dim3(128, 4), 256>>>(nodes);
    k_ab<<<128, 256>>>(nodes);
    k_passA<<<dim3(4, 256), 256>>>(deg, bond, cutp);
    k_inv<<<64, 256>>>();
    k_transp<<<dim3(128, 8), 256>>>();
    k_ln<<<NN, 256>>>(outln);
    k_mma<<<dim3(64, 4, 2), 256, SMEM_MMA>>>();
    k_epi<<<1024, 256>>>(out);
}

// round 10
// speedup vs baseline: 3.2026x; 1.2694x over previous
#include <cuda_runtime.h>
#include <cuda_bf16.h>
#include <math.h>
#include <stdint.h>

#define NN 4096
#define NEG_INF -1e9f
#define L2E 1.4426950408889634f

// ---------------- scratch ----------------
__device__ __align__(16) float g_mask[(size_t)NN * NN];
__device__ __align__(16) float g_NW[(size_t)NN * 512];
__device__ __align__(16) unsigned short g_Whi[(size_t)256 * NN];   // bf16 rn(W^T * inv)
__device__ __align__(16) float g_ab[NN * 8];
__device__ __align__(16) float g_W512[128 * 512];
__device__ __align__(16) float g_Wab[128 * 8];
__device__ __align__(16) float g_den[NN * 4];
__device__ __align__(16) float g_inv[NN * 4];
__device__ __align__(16) float g_part[2][(size_t)NN * 256];

__device__ __forceinline__ uint32_t smem_u32(const void* p) {
    uint32_t a;
    asm("{ .reg .u64 tmp; cvta.to.shared.u64 tmp, %1; cvt.u32.u64 %0, tmp; }" : "=r"(a) : "l"(p));
    return a;
}
__device__ __forceinline__ void mma_bf16(float* d, const uint32_t* a, uint32_t b0, uint32_t b1) {
    asm volatile(
        "mma.sync.aligned.m16n8k16.row.col.f32.bf16.bf16.f32 "
        "{%0,%1,%2,%3}, {%4,%5,%6,%7}, {%8,%9}, {%0,%1,%2,%3};"
        : "+f"(d[0]), "+f"(d[1]), "+f"(d[2]), "+f"(d[3])
        : "r"(a[0]), "r"(a[1]), "r"(a[2]), "r"(a[3]), "r"(b0), "r"(b1));
}
#define LDSM4(r, a) asm volatile("ldmatrix.sync.aligned.m8n8.x4.shared.b16 {%0,%1,%2,%3}, [%4];" \
    : "=r"((r)[0]), "=r"((r)[1]), "=r"((r)[2]), "=r"((r)[3]) : "r"(a))
__device__ __forceinline__ void cp_async16(uint32_t dst, const void* src) {
    asm volatile("cp.async.ca.shared.global [%0], [%1], 16;" :: "r"(dst), "l"(src));
}
#define CP_COMMIT()  asm volatile("cp.async.commit_group;" ::: "memory")
#define CP_WAIT(n)   asm volatile("cp.async.wait_group %0;" :: "n"(n) : "memory")

// ---------------- K_prep ----------------
__global__ void k_prep(const float* __restrict__ pp, const float* __restrict__ ssrc,
                       const float* __restrict__ stgt, const float* __restrict__ skw) {
    int idx = blockIdx.x * 256 + threadIdx.x;
    if (idx < 128 * 512) {
        int f = idx >> 9, c = idx & 511;
        float v;
        if (c < 256) { int h = c >> 6, o = c & 63; v = pp[h * 128 * 64 + f * 64 + o]; }
        else         { int cc = c - 256;           v = skw[cc * 128 + f]; }
        g_W512[f * 512 + c] = v;
    }
    if (idx < 128 * 8) {
        int f = idx >> 3, c = idx & 7;
        int h = c & 3;
        const float* sc = (c < 4) ? ssrc : stgt;
        float acc = 0.f;
        #pragma unroll
        for (int o = 0; o < 64; ++o) acc += pp[h * 128 * 64 + f * 64 + o] * sc[h * 64 + o];
        g_Wab[f * 8 + c] = acc;
    }
    if (idx < NN * 4) g_den[idx] = 0.f;
}

// ---------------- K0b: NW = nodes @ W512 ----------------
__global__ void __launch_bounds__(256) k_gemm_nw(const float* __restrict__ nodes) {
    __shared__ float sN[32][128];
    __shared__ float sW[32][128];
    int t = threadIdx.x;
    int r0 = blockIdx.x * 32;
    int c0 = blockIdx.y * 128;
    #pragma unroll
    for (int k = 0; k < 16; ++k) {
        int e = t + k * 256; int kk = e & 127, rr = e >> 7;
        sN[rr][kk] = nodes[(r0 + rr) * 128 + kk];
    }
    float acc[4][4] = {};
    int rg = t >> 5, cg = t & 31;
    for (int kc = 0; kc < 4; ++kc) {
        __syncthreads();
        #pragma unroll
        for (int k = 0; k < 16; ++k) {
            int e = t + k * 256; int cc = e & 127, kk = e >> 7;
            sW[kk][cc] = g_W512[(kc * 32 + kk) * 512 + c0 + cc];
        }
        __syncthreads();
        #pragma unroll
        for (int k = 0; k < 32; ++k) {
            float4 b = *(const float4*)&sW[k][cg * 4];
            #pragma unroll
            for (int q = 0; q < 4; ++q) {
                float a = sN[rg * 4 + q][kc * 32 + k];
                acc[q][0] += a * b.x; acc[q][1] += a * b.y;
                acc[q][2] += a * b.z; acc[q][3] += a * b.w;
            }
        }
    }
    #pragma unroll
    for (int q = 0; q < 4; ++q) {
        *(float4*)&g_NW[(size_t)(r0 + rg * 4 + q) * 512 + c0 + cg * 4] =
            make_float4(acc[q][0], acc[q][1], acc[q][2], acc[q][3]);
    }
}

// ---------------- K0c ----------------
__global__ void k_ab(const float* __restrict__ nodes) {
    int idx = blockIdx.x * 256 + threadIdx.x;
    int n = idx >> 3, c = idx & 7;
    float acc = 0.f;
    #pragma unroll 8
    for (int f = 0; f < 128; ++f) acc += __ldg(&nodes[n * 128 + f]) * g_Wab[f * 8 + c];
    g_ab[idx] = acc;
}

// ---------------- K_A: R6 config restored (scalar, grid 16x64, 41us measured) ----------------
__global__ void __launch_bounds__(256) k_passA(const float* __restrict__ deg,
                                               const float* __restrict__ bond,
                                               const float* __restrict__ cutp) {
    __shared__ float4 sa[64];
    int t = threadIdx.x;
    int j = blockIdx.x * 256 + t;
    int i0 = blockIdx.y * 64;
    float cut = cutp[0];
    float4 b4 = *(const float4*)&g_ab[j * 8 + 4];
    if (t < 64) sa[t] = *(const float4*)&g_ab[(i0 + t) * 8];
    __syncthreads();
    float d0 = 0.f, d1 = 0.f, d2 = 0.f, d3 = 0.f;
    #pragma unroll 4
    for (int il = 0; il < 64; ++il) {
        size_t off = (size_t)(i0 + il) * NN + j;
        float dd = deg[off], bb = bond[off];
        float wdm = dd + bb;
        float m = (wdm > 0.f) ? wdm : ((bb > cut) ? (bb + wdm) : NEG_INF);
        g_mask[off] = m;
        float4 a = sa[il];
        float x0 = a.x + b4.x; x0 = fmaxf(x0, 0.2f * x0); d0 += __expf(x0 + m);
        float x1 = a.y + b4.y; x1 = fmaxf(x1, 0.2f * x1); d1 += __expf(x1 + m);
        float x2 = a.z + b4.z; x2 = fmaxf(x2, 0.2f * x2); d2 += __expf(x2 + m);
        float x3 = a.w + b4.w; x3 = fmaxf(x3, 0.2f * x3); d3 += __expf(x3 + m);
    }
    atomicAdd(&g_den[j * 4 + 0], d0);
    atomicAdd(&g_den[j * 4 + 1], d1);
    atomicAdd(&g_den[j * 4 + 2], d2);
    atomicAdd(&g_den[j * 4 + 3], d3);
}

__global__ void k_inv() {
    int i = blockIdx.x * 256 + threadIdx.x;
    g_inv[i] = 1.0f / g_den[i];
}

// ---------------- K_T: W^T[hf][j] = rn_bf16(NW[j][hf] * inv[j][h]) ----------------
__global__ void __launch_bounds__(256) k_transp() {
    __shared__ float tile[32][33];
    int t = threadIdx.x;
    int j0 = blockIdx.x * 32, hf0 = blockIdx.y * 32;
    int col = t & 31, rq = t >> 5;
    #pragma unroll
    for (int q = 0; q < 4; ++q) {
        int jj = rq + q * 8;
        int hf = hf0 + col;
        tile[jj][col] = g_NW[(size_t)(j0 + jj) * 512 + hf] * g_inv[(j0 + jj) * 4 + (hf >> 6)];
    }
    __syncthreads();
    #pragma unroll
    for (int q = 0; q < 4; ++q) {
        int jj = rq + q * 8;
        float w = tile[col][jj];
        __nv_bfloat16 b = __float2bfloat16_rn(w);
        g_Whi[(size_t)(hf0 + jj) * NN + j0 + col] = *(unsigned short*)&b;
    }
}

// ---------------- K_LN ----------------
__global__ void __launch_bounds__(256) k_ln(float* __restrict__ outln) {
    __shared__ float red[256];
    __shared__ float red2[256];
    int r = blockIdx.x, t = threadIdx.x;
    const float4* row = (const float4*)&g_mask[(size_t)r * NN];
    float4 v[4];
    float s = 0.f, sq = 0.f;
    #pragma unroll
    for (int k = 0; k < 4; ++k) {
        v[k] = row[t + k * 256];
        s  += v[k].x + v[k].y + v[k].z + v[k].w;
        sq += v[k].x * v[k].x + v[k].y * v[k].y + v[k].z * v[k].z + v[k].w * v[k].w;
    }
    red[t] = s; red2[t] = sq;
    __syncthreads();
    for (int off = 128; off > 0; off >>= 1) {
        if (t < off) { red[t] += red[t + off]; red2[t] += red2[t + off]; }
        __syncthreads();
    }
    float mu  = red[0] * (1.0f / NN);
    float var = red2[0] * (1.0f / NN) - mu * mu;
    float rstd = rsqrtf(var + 1e-5f);
    float4* o = (float4*)&outln[(size_t)r * NN];
    #pragma unroll
    for (int k = 0; k < 4; ++k) {
        float4 w = v[k];
        w.x = (w.x - mu) * rstd; w.y = (w.y - mu) * rstd;
        w.z = (w.z - mu) * rstd; w.w = (w.w - mu) * rstd;
        o[t + k * 256] = w;
    }
}

// ---------------- K_MMA: pipelined HMMA single-term (P rn-bf16 x W rn-bf16) ----------------
// grid (64 i, 4 head, 2 j-half). 8 warps: fh(2: 32 f) x ih(4: 16 rows).
// smem: sP 8KB | sW 2x8KB | sbv 512B = ~24.5KB
#define PBUF 8192
#define WBUF 8192
#define SMEM_MMA (PBUF + 2 * WBUF + 512)

__global__ void __launch_bounds__(256) k_mma(void) {
    extern __shared__ char sm[];
    char* sP = sm;                                   // 8KB: 64i x 64j bf16 swizzled
    float* sbv = (float*)(sm + PBUF + 2 * WBUF);     // [buf][64]
    uint32_t smP = smem_u32(sm);
    uint32_t smW = smP + PBUF;

    int t = threadIdx.x;
    int l = t & 31;
    int wid = t >> 5;
    int fh = wid & 1, ih = wid >> 1;
    int head = blockIdx.y;
    int i0 = blockIdx.x * 64;
    int jz = blockIdx.z;
    int jstart = jz * 2048;

    // staging roles: P
    int iloc = t >> 2;             // 0..63
    int jq = (t & 3) * 16;
    float aL = g_ab[(i0 + iloc) * 8 + head];

    // LDSM lane-constant parts
    int lt = l >> 3, lr = l & 7;
    uint32_t swz = (uint32_t)(lr << 4);
    uint32_t aRow0 = (uint32_t)((ih * 16 + lr + (lt & 1) * 8) * 128);
    uint32_t aColT = (uint32_t)(16 * (lt >> 1));
    uint32_t bRow0 = (uint32_t)((fh * 32 + (lt >> 1) * 8 + lr) * 128);
    uint32_t bColT = (uint32_t)(16 * (lt & 1));

    // W cp.async roles: wr = t>>2 row (0..63), 2 x 16B chunks of the 128B row
    int wr = t >> 2;
    int wc0 = (t & 3) * 2;
    const unsigned short* whsrc = &g_Whi[(size_t)(head * 64 + wr) * NN + jstart];
    uint32_t wdstHi = smW + (uint32_t)(wr * 128);
    uint32_t wswz = (uint32_t)((wr & 7) << 4);

    float d[4][4] = {};
    float mv[16];

    // ---- prologue ----
    {
        const float4* mrow = (const float4*)&g_mask[(size_t)(i0 + iloc) * NN + jstart + jq];
        #pragma unroll
        for (int q = 0; q < 4; ++q) *(float4*)&mv[q * 4] = mrow[q];
        if (t < 64) sbv[t] = g_ab[(jstart + t) * 8 + 4 + head];
        #pragma unroll
        for (int q = 0; q < 2; ++q) {
            int c = wc0 + q;
            uint32_t dsw = (uint32_t)(c * 16) ^ wswz;
            cp_async16(wdstHi + dsw, whsrc + c * 8);
        }
        CP_COMMIT();
        CP_WAIT(0);
        __syncthreads();
    }

    for (int ch = 0; ch < 32; ++ch) {
        int buf = ch & 1;
        int jb = ch * 64;
        // ---- stage P (exp, rn bf16) ----
        {
            const float* bvec = &sbv[buf * 64];
            uint32_t hpp[8];
            #pragma unroll
            for (int q = 0; q < 8; ++q) {
                float2 b2 = *(const float2*)&bvec[jq + q * 2];
                float x0 = aL + b2.x, x1 = aL + b2.y;
                x0 = fmaxf(x0, 0.2f * x0); x1 = fmaxf(x1, 0.2f * x1);
                float e0 = (x0 + mv[q * 2]) * L2E;
                float e1 = (x1 + mv[q * 2 + 1]) * L2E;
                float p0, p1;
                asm("ex2.approx.ftz.f32 %0, %1;" : "=f"(p0) : "f"(e0));
                asm("ex2.approx.ftz.f32 %0, %1;" : "=f"(p1) : "f"(e1));
                asm("cvt.rn.bf16x2.f32 %0, %1, %2;" : "=r"(hpp[q]) : "f"(p1), "f"(p0));
            }
            uint32_t sw = (uint32_t)((iloc & 7) << 4);
            uint32_t o1 = (uint32_t)(iloc * 128) + ((uint32_t)(2 * jq) ^ sw);
            uint32_t o2 = (uint32_t)(iloc * 128) + ((uint32_t)(2 * jq + 16) ^ sw);
            *(uint4*)(sP + o1) = make_uint4(hpp[0], hpp[1], hpp[2], hpp[3]);
            *(uint4*)(sP + o2) = make_uint4(hpp[4], hpp[5], hpp[6], hpp[7]);
        }
        // ---- prefetch next chunk ----
        if (ch < 31) {
            const float4* mrow = (const float4*)&g_mask[(size_t)(i0 + iloc) * NN + jstart + jb + 64 + jq];
            #pragma unroll
            for (int q = 0; q < 4; ++q) *(float4*)&mv[q * 4] = mrow[q];
            if (t < 64) sbv[(buf ^ 1) * 64 + t] = g_ab[(jstart + jb + 64 + t) * 8 + 4 + head];
            uint32_t wdst = wdstHi + (uint32_t)((buf ^ 1) * WBUF);
            const unsigned short* wh = whsrc + jb + 64;
            #pragma unroll
            for (int q = 0; q < 2; ++q) {
                int c = wc0 + q;
                uint32_t dsw = (uint32_t)(c * 16) ^ wswz;
                cp_async16(wdst + dsw, wh + c * 8);
            }
        }
        CP_COMMIT();
        CP_WAIT(1);
        __syncthreads();
        // ---- MMA (LDSM fragments): D += P*W ----
        uint32_t wbase = smW + (uint32_t)(buf * WBUF);
        #pragma unroll
        for (int kt = 0; kt < 4; ++kt) {
            uint32_t cA = ((uint32_t)(32 * kt) + aColT) ^ swz;
            uint32_t cB = ((uint32_t)(32 * kt) + bColT) ^ swz;
            uint32_t ap[4];
            LDSM4(ap, smP + aRow0 + cA);
            uint32_t bh0[4], bh1[4];
            LDSM4(bh0, wbase + bRow0 + cB);
            LDSM4(bh1, wbase + bRow0 + 2048 + cB);
            #pragma unroll
            for (int nt = 0; nt < 4; ++nt) {
                const uint32_t* bh = (nt < 2) ? bh0 : bh1;
                uint32_t b0h = bh[(nt & 1) * 2], b1h = bh[(nt & 1) * 2 + 1];
                mma_bf16(d[nt], ap, b0h, b1h);
            }
        }
        __syncthreads();
    }

    // ---- write partials ----
    #pragma unroll
    for (int nt = 0; nt < 4; ++nt) {
        int gcol = head * 64 + fh * 32 + nt * 8 + (l & 3) * 2;
        #pragma unroll
        for (int rr = 0; rr < 2; ++rr) {
            int row = i0 + ih * 16 + (l >> 2) + rr * 8;
            *(float2*)&g_part[jz][(size_t)row * 256 + gcol] =
                make_float2(d[nt][rr * 2 + 0], d[nt][rr * 2 + 1]);
        }
    }
}

// ---------------- K_EPI: out = elu(part0 + part1 + skip) ----------------
__global__ void __launch_bounds__(256) k_epi(float* __restrict__ out) {
    int id4 = blockIdx.x * 256 + threadIdx.x;
    int row = id4 >> 6;
    int c0 = (id4 & 63) * 4;
    float4 s0 = *(const float4*)&g_part[0][(size_t)row * 256 + c0];
    float4 s1 = *(const float4*)&g_part[1][(size_t)row * 256 + c0];
    float4 sk = *(const float4*)&g_NW[(size_t)row * 512 + 256 + c0];
    float v0 = s0.x + s1.x + sk.x;
    float v1 = s0.y + s1.y + sk.y;
    float v2 = s0.z + s1.z + sk.z;
    float v3 = s0.w + s1.w + sk.w;
    v0 = (v0 > 0.f) ? v0 : expm1f(v0);
    v1 = (v1 > 0.f) ? v1 : expm1f(v1);
    v2 = (v2 > 0.f) ? v2 : expm1f(v2);
    v3 = (v3 > 0.f) ? v3 : expm1f(v3);
    *(float4*)&out[(size_t)row * 256 + c0] = make_float4(v0, v1, v2, v3);
}

// ---------------- launch ----------------
extern "C" void kernel_launch(void* const* d_in, const int* in_sizes, int n_in,
                              void* d_out, int out_size) {
    const float* nodes = (const float*)d_in[0];
    const float* deg   = (const float*)d_in[1];
    const float* bond  = (const float*)d_in[3];
    const float* pp    = (const float*)d_in[4];
    const float* ssrc  = (const float*)d_in[5];
    const float* stgt  = (const float*)d_in[6];
    const float* skw   = (const float*)d_in[7];
    const float* cutp  = (const float*)d_in[8];

    float* out = (float*)d_out;
    float* outln = out + (size_t)NN * 256;

    static int smem_set = 0;
    if (!smem_set) {
        cudaFuncSetAttribute(k_mma, cudaFuncAttributeMaxDynamicSharedMemorySize, SMEM_MMA);
        smem_set = 1;
    }

    k_prep<<<256, 256>>>(pp, ssrc, stgt, skw);
    k_gemm_nw<<<dim3(128, 4), 256>>>(nodes);
    k_ab<<<128, 256>>>(nodes);
    k_passA<<<dim3(16, 64), 256>>>(deg, bond, cutp);
    k_inv<<<64, 256>>>();
    k_transp<<<dim3(128, 8), 256>>>();
    k_ln<<<NN, 256>>>(outln);
    k_mma<<<dim3(64, 4, 2), 256, SMEM_MMA>>>();
    k_epi<<<1024, 256>>>(out);
}